// round 12
// baseline (speedup 1.0000x reference)
#include <cuda_runtime.h>
#include <cuda_bf16.h>
#include <cstdint>
#include <stdint.h>
#include <math.h>

#define BATCH   128
#define N0      512
#define E_TOT   262144
#define F       128
#define NMAX    65536

// ---------------- static scratch ----------------
__device__ float g_bufA[NMAX * F];
__device__ float g_bufB[NMAX * F];
__device__ float g_dinv[NMAX];
__device__ float g_score[NMAX];
__device__ int   g_newid[NMAX];
__device__ int   g_perm[NMAX / 2];
__device__ float g_tanh[NMAX / 2];
__device__ int   g_indeg[NMAX];
__device__ int   g_offs[NMAX];
__device__ int   g_cursor[NMAX];
__device__ int   g_elist[E_TOT];
__device__ int   g_bagg[64];
__device__ int   g_bpre[64];
__device__ int   g_bstate[64];
__device__ int   g_srcA[E_TOT], g_dstA[E_TOT];
__device__ int   g_srcB[E_TOT], g_dstB[E_TOT];
__device__ int   g_ecnt2[1], g_ecnt3[1];
__device__ float g_z[BATCH * 2 * F];
__device__ float g_invn[3];
// packed W fragments: 3 stages x 8 kb x 128 n x 4 t4, uint4 = (hi_p0, lo_p0, hi_p1, lo_p1)
__device__ uint4 g_wp[3 * 8 * 128 * 4];

// ---------------- helpers ----------------
__device__ __forceinline__ void split2(float x0, float x1, unsigned& hi, unsigned& lo) {
    __nv_bfloat16 h0 = __float2bfloat16(x0);
    __nv_bfloat16 h1 = __float2bfloat16(x1);
    __nv_bfloat16 l0 = __float2bfloat16(x0 - __bfloat162float(h0));
    __nv_bfloat16 l1 = __float2bfloat16(x1 - __bfloat162float(h1));
    hi = (unsigned)__bfloat16_as_ushort(h0) | ((unsigned)__bfloat16_as_ushort(h1) << 16);
    lo = (unsigned)__bfloat16_as_ushort(l0) | ((unsigned)__bfloat16_as_ushort(l1) << 16);
}

__device__ __forceinline__ void mma_bf16(float d[4], const unsigned a[4], const unsigned b[2]) {
    asm volatile(
        "mma.sync.aligned.m16n8k16.row.col.f32.bf16.bf16.f32 "
        "{%0,%1,%2,%3}, {%4,%5,%6,%7}, {%8,%9}, {%0,%1,%2,%3};\n"
        : "+f"(d[0]), "+f"(d[1]), "+f"(d[2]), "+f"(d[3])
        : "r"(a[0]), "r"(a[1]), "r"(a[2]), "r"(a[3]), "r"(b[0]), "r"(b[1]));
}

// ---------------- kernels ----------------

__global__ void k_pnorm(const float* __restrict__ p1, const float* __restrict__ p2,
                        const float* __restrict__ p3, float* __restrict__ invn) {
    __shared__ float red[4];
    int tid = threadIdx.x;
    const float* ps[3] = {p1, p2, p3};
    for (int j = 0; j < 3; j++) {
        float v = ps[j][tid];
        float s = v * v;
#pragma unroll
        for (int o = 16; o > 0; o >>= 1) s += __shfl_down_sync(0xffffffffu, s, o);
        if ((tid & 31) == 0) red[tid >> 5] = s;
        __syncthreads();
        if (tid == 0) invn[j] = rsqrtf(red[0] + red[1] + red[2] + red[3]);
        __syncthreads();
    }
}

// pre-split W1..W3 into packed B-fragment layout (runs once, 24 blocks x 128 thr)
__global__ void k_wprep(const float* __restrict__ W1, const float* __restrict__ W2,
                        const float* __restrict__ W3, uint4* __restrict__ WP) {
    int s = blockIdx.x >> 3, kb = blockIdx.x & 7;
    const float* W = (s == 0) ? W1 : ((s == 1) ? W2 : W3);
    int n = threadIdx.x;
#pragma unroll
    for (int t4 = 0; t4 < 4; t4++) {
        int k0 = kb * 16 + 2 * t4;
        float a0 = W[(size_t)k0 * 128 + n];
        float a1 = W[(size_t)(k0 + 1) * 128 + n];
        float b0 = W[(size_t)(k0 + 8) * 128 + n];
        float b1 = W[(size_t)(k0 + 9) * 128 + n];
        unsigned h0, l0, h1, l1;
        split2(a0, a1, h0, l0);
        split2(b0, b1, h1, l1);
        WP[(((s * 8 + kb) * 128 + n) << 2) + t4] = make_uint4(h0, l0, h1, l1);
    }
}

// Y[rows][128] = X[rows][128] @ W[128][128]. bf16x3, smem-free, sync-free.
// Block = 128 rows x 64 cols (blockIdx.y = column half). Warp tile 16x64:
// 32 accumulator regs -> ~80 regs total -> 3 CTAs/SM for latency hiding.
__global__ __launch_bounds__(256, 3) void k_gemm_tc(const float* __restrict__ X,
                                                    const uint4* __restrict__ WP,
                                                    float* __restrict__ Y) {
    const int tid = threadIdx.x;
    const int lane = tid & 31;
    const int w = tid >> 5;
    const int g = lane >> 2;
    const int t4 = lane & 3;
    const int row0 = blockIdx.x * 128;
    const int cb = blockIdx.y * 64;
    const int mrow = w * 16;
    const size_t r0 = (size_t)(row0 + mrow + g) * 128;
    const size_t r1 = r0 + 8 * 128;

    float d[8][4];
#pragma unroll
    for (int nt = 0; nt < 8; nt++)
#pragma unroll
        for (int j = 0; j < 4; j++) d[nt][j] = 0.f;

#pragma unroll
    for (int kb = 0; kb < 8; kb++) {
        const int k0 = kb * 16 + 2 * t4;
        float2 x00 = *(const float2*)&X[r0 + k0];
        float2 x10 = *(const float2*)&X[r1 + k0];
        float2 x01 = *(const float2*)&X[r0 + k0 + 8];
        float2 x11 = *(const float2*)&X[r1 + k0 + 8];
        unsigned ahi[4], alo[4];
        split2(x00.x, x00.y, ahi[0], alo[0]);
        split2(x10.x, x10.y, ahi[1], alo[1]);
        split2(x01.x, x01.y, ahi[2], alo[2]);
        split2(x11.x, x11.y, ahi[3], alo[3]);

        const uint4* wp = WP + (((kb * 128 + cb) << 2) + t4);
#pragma unroll
        for (int nt = 0; nt < 8; nt++) {
            uint4 wv = wp[(nt * 8 + g) << 2];
            unsigned bhi[2] = {wv.x, wv.z};
            unsigned blo[2] = {wv.y, wv.w};
            mma_bf16(d[nt], ahi, bhi);
            mma_bf16(d[nt], ahi, blo);
            mma_bf16(d[nt], alo, bhi);
        }
    }

    // epilogue: d[nt] c0:(g, n0+2t4) c1:(g, n0+2t4+1) c2:(g+8,..) c3
#pragma unroll
    for (int nt = 0; nt < 8; nt++) {
        const int n0 = cb + nt * 8;
        float* y0 = &Y[r0 + n0 + 2 * t4];
        float* y1 = &Y[r1 + n0 + 2 * t4];
        *(float2*)y0 = make_float2(d[nt][0], d[nt][1]);
        *(float2*)y1 = make_float2(d[nt][2], d[nt][3]);
    }
}

__global__ void k_count(const int* __restrict__ dst, int* __restrict__ indeg) {
    int e = blockIdx.x * blockDim.x + threadIdx.x;
    if (e < E_TOT) atomicAdd(&indeg[dst[e]], 1);
}

// single-pass scan with decoupled lookback (grid <= 64 blocks, all resident)
__global__ __launch_bounds__(1024) void k_scanD(const int* __restrict__ indeg,
                                                int* __restrict__ offs,
                                                int* __restrict__ cursor,
                                                float* __restrict__ dinv,
                                                int* __restrict__ bagg,
                                                int* __restrict__ bpre,
                                                volatile int* __restrict__ bstate) {
    __shared__ int part[1024];
    __shared__ int s_excl;
    int tid = threadIdx.x, bid = blockIdx.x;
    int gi = bid * 1024 + tid;
    int d = indeg[gi];
    part[tid] = d;
    dinv[gi] = rsqrtf(1.0f + (float)d);
    __syncthreads();
#pragma unroll
    for (int off = 1; off < 1024; off <<= 1) {
        int v = (tid >= off) ? part[tid - off] : 0;
        __syncthreads();
        part[tid] += v;
        __syncthreads();
    }
    if (tid == 0) {
        int total = part[1023];
        int excl = 0;
        if (bid == 0) {
            bpre[0] = total;
            __threadfence();
            bstate[0] = 2;
        } else {
            bagg[bid] = total;
            __threadfence();
            bstate[bid] = 1;
            int j = bid - 1;
            while (true) {
                int st;
                while ((st = bstate[j]) == 0) { }
                if (st == 2) { excl += *((volatile int*)&bpre[j]); break; }
                excl += *((volatile int*)&bagg[j]);
                j--;
            }
            bpre[bid] = excl + total;
            __threadfence();
            bstate[bid] = 2;
        }
        s_excl = excl;
    }
    __syncthreads();
    int o = s_excl + part[tid] - d;
    offs[gi] = o;
    cursor[gi] = o;
}

__global__ void k_fill(const int* __restrict__ src, const int* __restrict__ dst,
                       const int* __restrict__ boundp, int boundc,
                       int* __restrict__ cursor, int* __restrict__ elist) {
    int e = blockIdx.x * blockDim.x + threadIdx.x;
    int bound = boundp ? *boundp : boundc;
    if (e >= bound) return;
    int pos = atomicAdd(&cursor[dst[e]], 1);
    elist[pos] = src[e];
}

// fused: GCN aggregate (gather) + bias + ReLU + pool score. 1 warp / node.
__global__ __launch_bounds__(256) void k_node(const float* __restrict__ hW,
                                              const float* __restrict__ bias,
                                              const float* __restrict__ dinv,
                                              const int* __restrict__ offs,
                                              const int* __restrict__ endo,
                                              const int* __restrict__ elist,
                                              const float* __restrict__ p,
                                              const float* __restrict__ invn,
                                              float* __restrict__ h,
                                              float* __restrict__ score, int n) {
    __shared__ float ps[128];
    __shared__ float bs[128];
    int tid = threadIdx.x, lane = tid & 31, w = tid >> 5;
    if (tid < 128) { ps[tid] = p[tid]; bs[tid] = bias[tid]; }
    __syncthreads();
    int i = blockIdx.x * 8 + w;
    if (i >= n) return;
    float dii = dinv[i];
    float s2 = dii * dii;
    float4 acc = *(const float4*)&hW[(long long)i * F + lane * 4];
    float4 bb = *(const float4*)&bs[lane * 4];
    acc.x = acc.x * s2 + bb.x; acc.y = acc.y * s2 + bb.y;
    acc.z = acc.z * s2 + bb.z; acc.w = acc.w * s2 + bb.w;
    int e = offs[i], ee = endo[i];
    for (; e < ee; e++) {
        int s = elist[e];
        float c = dinv[s] * dii;
        float4 v = *(const float4*)&hW[(long long)s * F + lane * 4];
        acc.x += v.x * c; acc.y += v.y * c; acc.z += v.z * c; acc.w += v.w * c;
    }
    acc.x = fmaxf(acc.x, 0.f); acc.y = fmaxf(acc.y, 0.f);
    acc.z = fmaxf(acc.z, 0.f); acc.w = fmaxf(acc.w, 0.f);
    *(float4*)&h[(long long)i * F + lane * 4] = acc;
    float4 pv = *(const float4*)&ps[lane * 4];
    float d = acc.x * pv.x + acc.y * pv.y + acc.z * pv.z + acc.w * pv.w;
#pragma unroll
    for (int o = 16; o > 0; o >>= 1) d += __shfl_down_sync(0xffffffffu, d, o);
    if (lane == 0) score[i] = d * invn[0];
}

// per-graph bitonic top-k; also zeroes next-stage indeg, scan flags, edge counter
__global__ void k_topk(const float* __restrict__ score, int n_per, int k,
                       int* __restrict__ perm, int* __restrict__ new_id,
                       float* __restrict__ tanhv,
                       int* __restrict__ zbuf, int zn,
                       int* __restrict__ zflag, int* __restrict__ bstate) {
    __shared__ float sc[512];
    __shared__ int id[512];
    int b = blockIdx.x, tid = threadIdx.x;
    int gidx = b * n_per + tid;
    if (gidx < zn) zbuf[gidx] = 0;
    if (gidx == 0 && zflag) zflag[0] = 0;
    if (gidx < 64 && bstate) bstate[gidx] = 0;
    int base = b * n_per;
    sc[tid] = score[base + tid];
    id[tid] = tid;
    new_id[base + tid] = -1;
    __syncthreads();
    for (int kk = 2; kk <= n_per; kk <<= 1) {
        for (int j = kk >> 1; j > 0; j >>= 1) {
            int ixj = tid ^ j;
            if (ixj > tid) {
                bool dir = ((tid & kk) == 0);
                float s1 = sc[tid], s2 = sc[ixj];
                int i1 = id[tid], i2 = id[ixj];
                bool swp = dir ? ((s2 > s1) || (s2 == s1 && i2 < i1))
                               : ((s1 > s2) || (s1 == s2 && i1 < i2));
                if (swp) { sc[tid] = s2; sc[ixj] = s1; id[tid] = i2; id[ixj] = i1; }
            }
            __syncthreads();
        }
    }
    if (tid < k) {
        int g = base + id[tid];
        perm[b * k + tid] = g;
        new_id[g] = b * k + tid;
        tanhv[b * k + tid] = tanhf(sc[tid]);
    }
}

// fused gather+readout (blocks 0..127) and relabel (blocks 128..). 256 threads.
__global__ __launch_bounds__(256) void k_gatherrelabel(
    const float* __restrict__ h, const int* __restrict__ perm,
    const float* __restrict__ tanhv, float* __restrict__ xk,
    float* __restrict__ z, int k, int acc,
    const int* __restrict__ srcI, const int* __restrict__ dstI,
    const int* __restrict__ boundp, int boundc,
    const int* __restrict__ new_id,
    int* __restrict__ srcO, int* __restrict__ dstO,
    int* __restrict__ ecnt, int* __restrict__ indeg) {
    int bid = blockIdx.x, tid = threadIdx.x;
    if (bid < 128) {
        __shared__ int sperm[256];
        __shared__ float stanh[256];
        __shared__ float mxb[256], smb[256];
        int b = bid;
        int f = tid & 127, half = tid >> 7;
        for (int j = tid; j < k; j += 256) {
            sperm[j] = perm[b * k + j];
            stanh[j] = tanhv[b * k + j];
        }
        __syncthreads();
        float mx = -INFINITY, sm = 0.f;
        for (int j = half; j < k; j += 2) {
            float v = h[(long long)sperm[j] * F + f] * stanh[j];
            if (xk) xk[(long long)(b * k + j) * F + f] = v;
            mx = fmaxf(mx, v);
            sm += v;
        }
        mxb[tid] = mx; smb[tid] = sm;
        __syncthreads();
        if (half == 0) {
            mx = fmaxf(mx, mxb[tid + 128]);
            sm = (sm + smb[tid + 128]) * (1.0f / (float)k);
            if (acc) {
                z[b * 256 + f] += mx;
                z[b * 256 + 128 + f] += sm;
            } else {
                z[b * 256 + f] = mx;
                z[b * 256 + 128 + f] = sm;
            }
        }
    } else {
        int e = (bid - 128) * 256 + tid;
        int bound = boundp ? *boundp : boundc;
        if (e >= bound) return;
        int ns = new_id[srcI[e]];
        int nd = new_id[dstI[e]];
        if (ns >= 0 && nd >= 0) {
            int idx = atomicAdd(ecnt, 1);
            srcO[idx] = ns;
            dstO[idx] = nd;
            atomicAdd(&indeg[nd], 1);
        }
    }
}

// final MLP + log_softmax
__global__ __launch_bounds__(128) void k_mlp(const float* __restrict__ z,
                      const float* __restrict__ L1, const float* __restrict__ bl1,
                      const float* __restrict__ L2, const float* __restrict__ bl2,
                      const float* __restrict__ L3, const float* __restrict__ bl3,
                      float* __restrict__ out) {
    __shared__ float zr[256];
    __shared__ float h1[128];
    __shared__ float h2[64];
    __shared__ float lg[2];
    int b = blockIdx.x, tid = threadIdx.x;
    zr[tid] = z[b * 256 + tid];
    zr[128 + tid] = z[b * 256 + 128 + tid];
    __syncthreads();
    float a = bl1[tid];
    for (int i = 0; i < 256; i++) a += zr[i] * L1[i * 128 + tid];
    h1[tid] = fmaxf(a, 0.f);
    __syncthreads();
    if (tid < 64) {
        float a2 = bl2[tid];
        for (int i = 0; i < 128; i++) a2 += h1[i] * L2[i * 64 + tid];
        h2[tid] = fmaxf(a2, 0.f);
    }
    __syncthreads();
    if (tid < 2) {
        float a3 = bl3[tid];
        for (int i = 0; i < 64; i++) a3 += h2[i] * L3[i * 2 + tid];
        lg[tid] = a3;
    }
    __syncthreads();
    if (tid == 0) {
        float m = fmaxf(lg[0], lg[1]);
        float lse = m + logf(expf(lg[0] - m) + expf(lg[1] - m));
        out[b * 2 + 0] = lg[0] - lse;
        out[b * 2 + 1] = lg[1] - lse;
    }
}

// ---------------- host orchestration ----------------
extern "C" void kernel_launch(void* const* d_in, const int* in_sizes, int n_in,
                              void* d_out, int out_size) {
    const float* x   = (const float*)d_in[0];
    const int*   src = (const int*)d_in[1];
    const int*   dst = (const int*)d_in[2];
    const float* W1 = (const float*)d_in[3];  const float* b1 = (const float*)d_in[4];
    const float* W2 = (const float*)d_in[5];  const float* b2 = (const float*)d_in[6];
    const float* W3 = (const float*)d_in[7];  const float* b3 = (const float*)d_in[8];
    const float* p1 = (const float*)d_in[9];
    const float* p2 = (const float*)d_in[10];
    const float* p3 = (const float*)d_in[11];
    const float* L1 = (const float*)d_in[12]; const float* bl1 = (const float*)d_in[13];
    const float* L2 = (const float*)d_in[14]; const float* bl2 = (const float*)d_in[15];
    const float* L3 = (const float*)d_in[16]; const float* bl3 = (const float*)d_in[17];
    float* out = (float*)d_out;

    float *A, *B, *dinv, *score, *tanhv, *z, *invn;
    int *newid, *perm, *indeg, *offs, *cursor, *elist, *bagg, *bpre, *bstate;
    int *srcA, *dstA, *srcB, *dstB, *ecnt2, *ecnt3;
    uint4 *wp;
    cudaGetSymbolAddress((void**)&A, g_bufA);
    cudaGetSymbolAddress((void**)&B, g_bufB);
    cudaGetSymbolAddress((void**)&dinv, g_dinv);
    cudaGetSymbolAddress((void**)&score, g_score);
    cudaGetSymbolAddress((void**)&newid, g_newid);
    cudaGetSymbolAddress((void**)&perm, g_perm);
    cudaGetSymbolAddress((void**)&tanhv, g_tanh);
    cudaGetSymbolAddress((void**)&indeg, g_indeg);
    cudaGetSymbolAddress((void**)&offs, g_offs);
    cudaGetSymbolAddress((void**)&cursor, g_cursor);
    cudaGetSymbolAddress((void**)&elist, g_elist);
    cudaGetSymbolAddress((void**)&bagg, g_bagg);
    cudaGetSymbolAddress((void**)&bpre, g_bpre);
    cudaGetSymbolAddress((void**)&bstate, g_bstate);
    cudaGetSymbolAddress((void**)&srcA, g_srcA);
    cudaGetSymbolAddress((void**)&dstA, g_dstA);
    cudaGetSymbolAddress((void**)&srcB, g_srcB);
    cudaGetSymbolAddress((void**)&dstB, g_dstB);
    cudaGetSymbolAddress((void**)&ecnt2, g_ecnt2);
    cudaGetSymbolAddress((void**)&ecnt3, g_ecnt3);
    cudaGetSymbolAddress((void**)&z, g_z);
    cudaGetSymbolAddress((void**)&invn, g_invn);
    cudaGetSymbolAddress((void**)&wp, g_wp);

    const int EB = 256, EG = E_TOT / EB;

    // copy-engine zeroing (not kernel launches)
    cudaMemsetAsync(indeg, 0, 65536 * sizeof(int));
    cudaMemsetAsync(bstate, 0, 64 * sizeof(int));

    // ---------- stage 1: n=65536, n_per=512, k=256 ----------
    {
        const int n = 65536, n_per = 512, k = 256;
        k_pnorm<<<1, 128>>>(p1, p2, p3, invn);                  // 2 (poison=1)
        k_count<<<EG, EB>>>(dst, indeg);                         // 3
        k_wprep<<<24, 128>>>(W1, W2, W3, wp);                    // 4
        k_gemm_tc<<<dim3(n / 128, 2), 256>>>(x, wp, A);          // 5 <- ncu capture
        k_scanD<<<n / 1024, 1024>>>(indeg, offs, cursor, dinv, bagg, bpre, bstate);
        k_fill<<<EG, EB>>>(src, dst, nullptr, E_TOT, cursor, elist);
        k_node<<<n / 8, 256>>>(A, b1, dinv, offs, cursor, elist, p1, invn + 0, B, score, n);
        k_topk<<<BATCH, n_per>>>(score, n_per, k, perm, newid, tanhv, indeg, 32768, ecnt2, bstate);
        k_gatherrelabel<<<128 + EG, 256>>>(B, perm, tanhv, A, z, k, 0,
                                           src, dst, nullptr, E_TOT, newid,
                                           srcA, dstA, ecnt2, indeg);
    }
    // ---------- stage 2: n=32768, n_per=256, k=128 ----------
    {
        const int n = 32768, n_per = 256, k = 128;
        k_gemm_tc<<<dim3(n / 128, 2), 256>>>(A, wp + 4096, B);
        k_scanD<<<n / 1024, 1024>>>(indeg, offs, cursor, dinv, bagg, bpre, bstate);
        k_fill<<<EG, EB>>>(srcA, dstA, ecnt2, 0, cursor, elist);
        k_node<<<n / 8, 256>>>(B, b2, dinv, offs, cursor, elist, p2, invn + 1, A, score, n);
        k_topk<<<BATCH, n_per>>>(score, n_per, k, perm, newid, tanhv, indeg, 16384, ecnt3, bstate);
        k_gatherrelabel<<<128 + EG, 256>>>(A, perm, tanhv, B, z, k, 1,
                                           srcA, dstA, ecnt2, 0, newid,
                                           srcB, dstB, ecnt3, indeg);
    }
    // ---------- stage 3: n=16384, n_per=128, k=64 ----------
    {
        const int n = 16384, n_per = 128, k = 64;
        k_gemm_tc<<<dim3(n / 128, 2), 256>>>(B, wp + 8192, A);
        k_scanD<<<n / 1024, 1024>>>(indeg, offs, cursor, dinv, bagg, bpre, bstate);
        k_fill<<<EG, EB>>>(srcB, dstB, ecnt3, 0, cursor, elist);
        k_node<<<n / 8, 256>>>(A, b3, dinv, offs, cursor, elist, p3, invn + 2, B, score, n);
        k_topk<<<BATCH, n_per>>>(score, n_per, k, perm, newid, tanhv, nullptr, 0, nullptr, nullptr);
        k_gatherrelabel<<<128, 256>>>(B, perm, tanhv, nullptr, z, k, 1,
                                      nullptr, nullptr, nullptr, 0, nullptr,
                                      nullptr, nullptr, nullptr, nullptr);
    }
    // ---------- MLP head ----------
    k_mlp<<<BATCH, 128>>>(z, L1, bl1, L2, bl2, L3, bl3, out);
}

// round 13
// speedup vs baseline: 1.3256x; 1.3256x over previous
#include <cuda_runtime.h>
#include <cuda_bf16.h>
#include <cstdint>
#include <stdint.h>
#include <math.h>

#define BATCH   128
#define N0      512
#define E_TOT   262144
#define F       128
#define NMAX    65536

// ---------------- static scratch ----------------
__device__ float g_bufA[NMAX * F];
__device__ float g_bufB[NMAX * F];
__device__ float g_dinv[NMAX];
__device__ float g_score[NMAX];
__device__ int   g_newid[NMAX];
__device__ int   g_perm[NMAX / 2];
__device__ float g_tanh[NMAX / 2];
__device__ int   g_offs[NMAX];
__device__ int   g_endo[NMAX];
__device__ int   g_elist[E_TOT];
__device__ int   g_srcA[E_TOT], g_dstA[E_TOT];
__device__ int   g_srcB[E_TOT], g_dstB[E_TOT];
__device__ int   g_gcnt2[BATCH], g_gcnt3[BATCH];
__device__ float g_z[BATCH * 2 * F];
__device__ float g_invn[3];

// ---------------- helpers ----------------
__device__ __forceinline__ void split2(float x0, float x1, unsigned& hi, unsigned& lo) {
    __nv_bfloat16 h0 = __float2bfloat16(x0);
    __nv_bfloat16 h1 = __float2bfloat16(x1);
    __nv_bfloat16 l0 = __float2bfloat16(x0 - __bfloat162float(h0));
    __nv_bfloat16 l1 = __float2bfloat16(x1 - __bfloat162float(h1));
    hi = (unsigned)__bfloat16_as_ushort(h0) | ((unsigned)__bfloat16_as_ushort(h1) << 16);
    lo = (unsigned)__bfloat16_as_ushort(l0) | ((unsigned)__bfloat16_as_ushort(l1) << 16);
}

__device__ __forceinline__ void mma_bf16(float d[4], const unsigned a[4], const unsigned b[2]) {
    asm volatile(
        "mma.sync.aligned.m16n8k16.row.col.f32.bf16.bf16.f32 "
        "{%0,%1,%2,%3}, {%4,%5,%6,%7}, {%8,%9}, {%0,%1,%2,%3};\n"
        : "+f"(d[0]), "+f"(d[1]), "+f"(d[2]), "+f"(d[3])
        : "r"(a[0]), "r"(a[1]), "r"(a[2]), "r"(a[3]), "r"(b[0]), "r"(b[1]));
}

// ---------------- kernels ----------------

__global__ void k_pnorm(const float* __restrict__ p1, const float* __restrict__ p2,
                        const float* __restrict__ p3, float* __restrict__ invn) {
    __shared__ float red[4];
    int tid = threadIdx.x;
    const float* ps[3] = {p1, p2, p3};
    for (int j = 0; j < 3; j++) {
        float v = ps[j][tid];
        float s = v * v;
#pragma unroll
        for (int o = 16; o > 0; o >>= 1) s += __shfl_down_sync(0xffffffffu, s, o);
        if ((tid & 31) == 0) red[tid >> 5] = s;
        __syncthreads();
        if (tid == 0) invn[j] = rsqrtf(red[0] + red[1] + red[2] + red[3]);
        __syncthreads();
    }
}

// GEMM (round-9 proven): 128x128 block tile, 8 warps, bf16x3, smem staged.
__global__ __launch_bounds__(256, 2) void k_gemm_tc(const float* __restrict__ X,
                                                    const float* __restrict__ W,
                                                    float* __restrict__ Y) {
    __shared__ uint2 Xs[128 * 12];
    __shared__ uint2 Ws[128 * 12];

    const int tid = threadIdx.x;
    const int lane = tid & 31;
    const int w = tid >> 5;
    const int g = lane >> 2;
    const int t4 = lane & 3;
    const int row0 = blockIdx.x * 128;
    const int mrow = w * 16;

    float d[16][4];
#pragma unroll
    for (int nt = 0; nt < 16; nt++)
#pragma unroll
        for (int j = 0; j < 4; j++) d[nt][j] = 0.f;

    const int xr = tid >> 1;
    const int xh = tid & 1;

    for (int kb = 0; kb < 128; kb += 16) {
        {
            const float* xrow = &X[(size_t)(row0 + xr) * 128 + kb + 8 * xh];
            float4 v1 = *(const float4*)&xrow[0];
            float4 v2 = *(const float4*)&xrow[4];
            unsigned h, l;
            split2(v1.x, v1.y, h, l); Xs[xr * 12 + 4 * xh + 0] = make_uint2(h, l);
            split2(v1.z, v1.w, h, l); Xs[xr * 12 + 4 * xh + 1] = make_uint2(h, l);
            split2(v2.x, v2.y, h, l); Xs[xr * 12 + 4 * xh + 2] = make_uint2(h, l);
            split2(v2.z, v2.w, h, l); Xs[xr * 12 + 4 * xh + 3] = make_uint2(h, l);
        }
        {
            int n = tid & 127, kh = tid >> 7;
#pragma unroll
            for (int j = 0; j < 4; j++) {
                int k = kb + 8 * kh + 2 * j;
                float w0 = W[(size_t)k * 128 + n];
                float w1 = W[(size_t)(k + 1) * 128 + n];
                unsigned h, l;
                split2(w0, w1, h, l);
                Ws[n * 12 + 4 * kh + j] = make_uint2(h, l);
            }
        }
        __syncthreads();
        {
            uint2 xa0 = Xs[(mrow + g) * 12 + t4];
            uint2 xa1 = Xs[(mrow + g + 8) * 12 + t4];
            uint2 xa2 = Xs[(mrow + g) * 12 + 4 + t4];
            uint2 xa3 = Xs[(mrow + g + 8) * 12 + 4 + t4];
            unsigned ahi[4] = {xa0.x, xa1.x, xa2.x, xa3.x};
            unsigned alo[4] = {xa0.y, xa1.y, xa2.y, xa3.y};
#pragma unroll
            for (int nt = 0; nt < 16; nt++) {
                uint2 wb0 = Ws[(nt * 8 + g) * 12 + t4];
                uint2 wb1 = Ws[(nt * 8 + g) * 12 + 4 + t4];
                unsigned bhi[2] = {wb0.x, wb1.x};
                unsigned blo[2] = {wb0.y, wb1.y};
                mma_bf16(d[nt], ahi, bhi);
                mma_bf16(d[nt], ahi, blo);
                mma_bf16(d[nt], alo, bhi);
            }
        }
        __syncthreads();
    }

#pragma unroll
    for (int nt = 0; nt < 16; nt++) {
        const int n0 = nt * 8;
        float* y0 = &Y[(size_t)(row0 + mrow + g) * 128 + n0 + 2 * t4];
        float* y1 = &Y[(size_t)(row0 + mrow + g + 8) * 128 + n0 + 2 * t4];
        *(float2*)y0 = make_float2(d[nt][0], d[nt][1]);
        *(float2*)y1 = make_float2(d[nt][2], d[nt][3]);
    }
}

// per-graph CSR build: 1 block/graph, edges in [b*2048, b*2048+cnt).
// smem histogram + smem scan + smem-atomic fill. Also writes dinv.
__global__ __launch_bounds__(512) void k_csr(const int* __restrict__ src,
                                             const int* __restrict__ dst,
                                             const int* __restrict__ cntp, int n_per,
                                             int* __restrict__ offs, int* __restrict__ endo,
                                             float* __restrict__ dinv, int* __restrict__ elist) {
    __shared__ int deg[512];
    __shared__ int scn[512];
    __shared__ int cur[512];
    int b = blockIdx.x, tid = threadIdx.x;
    int nbase = b * n_per;
    int ebase = b * 2048;
    int cnt = cntp ? cntp[b] : 2048;
    deg[tid] = 0;
    __syncthreads();
    for (int e = tid; e < cnt; e += 512)
        atomicAdd(&deg[dst[ebase + e] - nbase], 1);
    __syncthreads();
    int d = (tid < n_per) ? deg[tid] : 0;
    scn[tid] = d;
    __syncthreads();
#pragma unroll
    for (int off = 1; off < 512; off <<= 1) {
        int v = (tid >= off) ? scn[tid - off] : 0;
        __syncthreads();
        scn[tid] += v;
        __syncthreads();
    }
    int excl = scn[tid] - d;
    if (tid < n_per) {
        offs[nbase + tid] = ebase + excl;
        endo[nbase + tid] = ebase + excl + d;
        dinv[nbase + tid] = rsqrtf(1.0f + (float)d);
        cur[tid] = ebase + excl;
    }
    __syncthreads();
    for (int e = tid; e < cnt; e += 512) {
        int dd = dst[ebase + e] - nbase;
        int pos = atomicAdd(&cur[dd], 1);
        elist[pos] = src[ebase + e];
    }
}

// fused: GCN aggregate (gather, unroll x2) + bias + ReLU + pool score. 1 warp/node.
__global__ __launch_bounds__(256) void k_node(const float* __restrict__ hW,
                                              const float* __restrict__ bias,
                                              const float* __restrict__ dinv,
                                              const int* __restrict__ offs,
                                              const int* __restrict__ endo,
                                              const int* __restrict__ elist,
                                              const float* __restrict__ p,
                                              const float* __restrict__ invn,
                                              float* __restrict__ h,
                                              float* __restrict__ score, int n) {
    __shared__ float ps[128];
    __shared__ float bs[128];
    int tid = threadIdx.x, lane = tid & 31, w = tid >> 5;
    if (tid < 128) { ps[tid] = p[tid]; bs[tid] = bias[tid]; }
    __syncthreads();
    int i = blockIdx.x * 8 + w;
    if (i >= n) return;
    float dii = dinv[i];
    float s2 = dii * dii;
    float4 acc = *(const float4*)&hW[(size_t)i * F + lane * 4];
    float4 bb = *(const float4*)&bs[lane * 4];
    acc.x = acc.x * s2 + bb.x; acc.y = acc.y * s2 + bb.y;
    acc.z = acc.z * s2 + bb.z; acc.w = acc.w * s2 + bb.w;
    float4 acc2 = make_float4(0.f, 0.f, 0.f, 0.f);
    int e = offs[i], ee = endo[i];
    for (; e + 1 < ee; e += 2) {
        int s0 = elist[e], s1 = elist[e + 1];
        float c0 = dinv[s0] * dii, c1 = dinv[s1] * dii;
        float4 v0 = *(const float4*)&hW[(size_t)s0 * F + lane * 4];
        float4 v1 = *(const float4*)&hW[(size_t)s1 * F + lane * 4];
        acc.x += v0.x * c0;  acc.y += v0.y * c0;
        acc.z += v0.z * c0;  acc.w += v0.w * c0;
        acc2.x += v1.x * c1; acc2.y += v1.y * c1;
        acc2.z += v1.z * c1; acc2.w += v1.w * c1;
    }
    if (e < ee) {
        int s0 = elist[e];
        float c0 = dinv[s0] * dii;
        float4 v0 = *(const float4*)&hW[(size_t)s0 * F + lane * 4];
        acc.x += v0.x * c0; acc.y += v0.y * c0;
        acc.z += v0.z * c0; acc.w += v0.w * c0;
    }
    acc.x += acc2.x; acc.y += acc2.y; acc.z += acc2.z; acc.w += acc2.w;
    acc.x = fmaxf(acc.x, 0.f); acc.y = fmaxf(acc.y, 0.f);
    acc.z = fmaxf(acc.z, 0.f); acc.w = fmaxf(acc.w, 0.f);
    *(float4*)&h[(size_t)i * F + lane * 4] = acc;
    float4 pv = *(const float4*)&ps[lane * 4];
    float d = acc.x * pv.x + acc.y * pv.y + acc.z * pv.z + acc.w * pv.w;
#pragma unroll
    for (int o = 16; o > 0; o >>= 1) d += __shfl_down_sync(0xffffffffu, d, o);
    if (lane == 0) score[i] = d * invn[0];
}

// per-graph bitonic top-k; zeroes next-stage per-graph edge counters
__global__ void k_topk(const float* __restrict__ score, int n_per, int k,
                       int* __restrict__ perm, int* __restrict__ new_id,
                       float* __restrict__ tanhv,
                       int* __restrict__ gcnt_next) {
    __shared__ float sc[512];
    __shared__ int id[512];
    int b = blockIdx.x, tid = threadIdx.x;
    if (tid == 0 && gcnt_next) gcnt_next[b] = 0;
    int base = b * n_per;
    sc[tid] = score[base + tid];
    id[tid] = tid;
    new_id[base + tid] = -1;
    __syncthreads();
    for (int kk = 2; kk <= n_per; kk <<= 1) {
        for (int j = kk >> 1; j > 0; j >>= 1) {
            int ixj = tid ^ j;
            if (ixj > tid) {
                bool dir = ((tid & kk) == 0);
                float s1 = sc[tid], s2 = sc[ixj];
                int i1 = id[tid], i2 = id[ixj];
                bool swp = dir ? ((s2 > s1) || (s2 == s1 && i2 < i1))
                               : ((s1 > s2) || (s1 == s2 && i1 < i2));
                if (swp) { sc[tid] = s2; sc[ixj] = s1; id[tid] = i2; id[ixj] = i1; }
            }
            __syncthreads();
        }
    }
    if (tid < k) {
        int g = base + id[tid];
        perm[b * k + tid] = g;
        new_id[g] = b * k + tid;
        tanhv[b * k + tid] = tanhf(sc[tid]);
    }
}

// fused gather+readout (blocks 0..127) and per-graph relabel/compact (blocks 128..)
__global__ __launch_bounds__(256) void k_gatherrelabel(
    const float* __restrict__ h, const int* __restrict__ perm,
    const float* __restrict__ tanhv, float* __restrict__ xk,
    float* __restrict__ z, int k, int acc,
    const int* __restrict__ srcI, const int* __restrict__ dstI,
    const int* __restrict__ cntp,
    const int* __restrict__ new_id,
    int* __restrict__ srcO, int* __restrict__ dstO,
    int* __restrict__ gcnt) {
    int bid = blockIdx.x, tid = threadIdx.x;
    if (bid < 128) {
        __shared__ int sperm[256];
        __shared__ float stanh[256];
        __shared__ float mxb[256], smb[256];
        int b = bid;
        int f = tid & 127, half = tid >> 7;
        for (int j = tid; j < k; j += 256) {
            sperm[j] = perm[b * k + j];
            stanh[j] = tanhv[b * k + j];
        }
        __syncthreads();
        float mx = -INFINITY, sm = 0.f;
        for (int j = half; j < k; j += 2) {
            float v = h[(size_t)sperm[j] * F + f] * stanh[j];
            if (xk) xk[(size_t)(b * k + j) * F + f] = v;
            mx = fmaxf(mx, v);
            sm += v;
        }
        mxb[tid] = mx; smb[tid] = sm;
        __syncthreads();
        if (half == 0) {
            mx = fmaxf(mx, mxb[tid + 128]);
            sm = (sm + smb[tid + 128]) * (1.0f / (float)k);
            if (acc) {
                z[b * 256 + f] += mx;
                z[b * 256 + 128 + f] += sm;
            } else {
                z[b * 256 + f] = mx;
                z[b * 256 + 128 + f] = sm;
            }
        }
    } else {
        int e = (bid - 128) * 256 + tid;
        int g = e >> 11;
        int el = e & 2047;
        int bound = cntp ? cntp[g] : 2048;
        if (el >= bound) return;
        int ns = new_id[srcI[e]];
        int nd = new_id[dstI[e]];
        if (ns >= 0 && nd >= 0) {
            int idx = atomicAdd(&gcnt[g], 1);
            srcO[g * 2048 + idx] = ns;
            dstO[g * 2048 + idx] = nd;
        }
    }
}

// final MLP + log_softmax
__global__ __launch_bounds__(128) void k_mlp(const float* __restrict__ z,
                      const float* __restrict__ L1, const float* __restrict__ bl1,
                      const float* __restrict__ L2, const float* __restrict__ bl2,
                      const float* __restrict__ L3, const float* __restrict__ bl3,
                      float* __restrict__ out) {
    __shared__ float zr[256];
    __shared__ float h1[128];
    __shared__ float h2[64];
    __shared__ float lg[2];
    int b = blockIdx.x, tid = threadIdx.x;
    zr[tid] = z[b * 256 + tid];
    zr[128 + tid] = z[b * 256 + 128 + tid];
    __syncthreads();
    float a = bl1[tid];
    for (int i = 0; i < 256; i++) a += zr[i] * L1[i * 128 + tid];
    h1[tid] = fmaxf(a, 0.f);
    __syncthreads();
    if (tid < 64) {
        float a2 = bl2[tid];
        for (int i = 0; i < 128; i++) a2 += h1[i] * L2[i * 64 + tid];
        h2[tid] = fmaxf(a2, 0.f);
    }
    __syncthreads();
    if (tid < 2) {
        float a3 = bl3[tid];
        for (int i = 0; i < 64; i++) a3 += h2[i] * L3[i * 2 + tid];
        lg[tid] = a3;
    }
    __syncthreads();
    if (tid == 0) {
        float m = fmaxf(lg[0], lg[1]);
        float lse = m + logf(expf(lg[0] - m) + expf(lg[1] - m));
        out[b * 2 + 0] = lg[0] - lse;
        out[b * 2 + 1] = lg[1] - lse;
    }
}

// ---------------- host orchestration ----------------
extern "C" void kernel_launch(void* const* d_in, const int* in_sizes, int n_in,
                              void* d_out, int out_size) {
    const float* x   = (const float*)d_in[0];
    const int*   src = (const int*)d_in[1];
    const int*   dst = (const int*)d_in[2];
    const float* W1 = (const float*)d_in[3];  const float* b1 = (const float*)d_in[4];
    const float* W2 = (const float*)d_in[5];  const float* b2 = (const float*)d_in[6];
    const float* W3 = (const float*)d_in[7];  const float* b3 = (const float*)d_in[8];
    const float* p1 = (const float*)d_in[9];
    const float* p2 = (const float*)d_in[10];
    const float* p3 = (const float*)d_in[11];
    const float* L1 = (const float*)d_in[12]; const float* bl1 = (const float*)d_in[13];
    const float* L2 = (const float*)d_in[14]; const float* bl2 = (const float*)d_in[15];
    const float* L3 = (const float*)d_in[16]; const float* bl3 = (const float*)d_in[17];
    float* out = (float*)d_out;

    float *A, *B, *dinv, *score, *tanhv, *z, *invn;
    int *newid, *perm, *offs, *endo, *elist;
    int *srcA, *dstA, *srcB, *dstB, *gcnt2, *gcnt3;
    cudaGetSymbolAddress((void**)&A, g_bufA);
    cudaGetSymbolAddress((void**)&B, g_bufB);
    cudaGetSymbolAddress((void**)&dinv, g_dinv);
    cudaGetSymbolAddress((void**)&score, g_score);
    cudaGetSymbolAddress((void**)&newid, g_newid);
    cudaGetSymbolAddress((void**)&perm, g_perm);
    cudaGetSymbolAddress((void**)&tanhv, g_tanh);
    cudaGetSymbolAddress((void**)&offs, g_offs);
    cudaGetSymbolAddress((void**)&endo, g_endo);
    cudaGetSymbolAddress((void**)&elist, g_elist);
    cudaGetSymbolAddress((void**)&srcA, g_srcA);
    cudaGetSymbolAddress((void**)&dstA, g_dstA);
    cudaGetSymbolAddress((void**)&srcB, g_srcB);
    cudaGetSymbolAddress((void**)&dstB, g_dstB);
    cudaGetSymbolAddress((void**)&gcnt2, g_gcnt2);
    cudaGetSymbolAddress((void**)&gcnt3, g_gcnt3);
    cudaGetSymbolAddress((void**)&z, g_z);
    cudaGetSymbolAddress((void**)&invn, g_invn);

    const int ERB = 1024;  // relabel blocks (x256 thr = 262144)

    // ---------- stage 1: n=65536, n_per=512, k=256 ----------
    {
        const int n = 65536, n_per = 512, k = 256;
        k_pnorm<<<1, 128>>>(p1, p2, p3, invn);                    // 2 (poison=1)
        k_gemm_tc<<<n / 128, 256>>>(x, W1, A);                    // 3
        k_csr<<<BATCH, 512>>>(src, dst, nullptr, n_per, offs, endo, dinv, elist); // 4
        k_node<<<n / 8, 256>>>(A, b1, dinv, offs, endo, elist, p1, invn + 0, B, score, n); // 5 <- ncu
        k_topk<<<BATCH, n_per>>>(score, n_per, k, perm, newid, tanhv, gcnt2);
        k_gatherrelabel<<<128 + ERB, 256>>>(B, perm, tanhv, A, z, k, 0,
                                            src, dst, nullptr, newid,
                                            srcA, dstA, gcnt2);
    }
    // ---------- stage 2: n=32768, n_per=256, k=128 ----------
    {
        const int n = 32768, n_per = 256, k = 128;
        k_gemm_tc<<<n / 128, 256>>>(A, W2, B);
        k_csr<<<BATCH, 512>>>(srcA, dstA, gcnt2, n_per, offs, endo, dinv, elist);
        k_node<<<n / 8, 256>>>(B, b2, dinv, offs, endo, elist, p2, invn + 1, A, score, n);
        k_topk<<<BATCH, n_per>>>(score, n_per, k, perm, newid, tanhv, gcnt3);
        k_gatherrelabel<<<128 + ERB, 256>>>(A, perm, tanhv, B, z, k, 1,
                                            srcA, dstA, gcnt2, newid,
                                            srcB, dstB, gcnt3);
    }
    // ---------- stage 3: n=16384, n_per=128, k=64 ----------
    {
        const int n = 16384, n_per = 128, k = 64;
        k_gemm_tc<<<n / 128, 256>>>(B, W3, A);
        k_csr<<<BATCH, 512>>>(srcB, dstB, gcnt3, n_per, offs, endo, dinv, elist);
        k_node<<<n / 8, 256>>>(A, b3, dinv, offs, endo, elist, p3, invn + 2, B, score, n);
        k_topk<<<BATCH, n_per>>>(score, n_per, k, perm, newid, tanhv, nullptr);
        k_gatherrelabel<<<128, 256>>>(B, perm, tanhv, nullptr, z, k, 1,
                                      nullptr, nullptr, nullptr, nullptr,
                                      nullptr, nullptr, nullptr);
    }
    // ---------- MLP head ----------
    k_mlp<<<BATCH, 128>>>(z, L1, bl1, L2, bl2, L3, bl3, out);
}

// round 14
// speedup vs baseline: 1.3938x; 1.0515x over previous
#include <cuda_runtime.h>
#include <cuda_bf16.h>
#include <cstdint>
#include <stdint.h>
#include <math.h>

#define BATCH   128
#define N0      512
#define E_TOT   262144
#define F       128
#define NMAX    65536

// ---------------- static scratch ----------------
__device__ float g_bufA[NMAX * F];
__device__ float g_bufB[NMAX * F];
__device__ float g_dinv[NMAX];
__device__ float g_score[NMAX];
__device__ int   g_offs[NMAX];
__device__ int   g_endo[NMAX];
__device__ int   g_elist[E_TOT];
__device__ int   g_srcA[E_TOT], g_dstA[E_TOT];
__device__ int   g_srcB[E_TOT], g_dstB[E_TOT];
__device__ int   g_gcnt2[BATCH], g_gcnt3[BATCH];
__device__ float g_z[BATCH * 2 * F];
__device__ float g_invn[3];

// ---------------- helpers ----------------
__device__ __forceinline__ void split2(float x0, float x1, unsigned& hi, unsigned& lo) {
    __nv_bfloat16 h0 = __float2bfloat16(x0);
    __nv_bfloat16 h1 = __float2bfloat16(x1);
    __nv_bfloat16 l0 = __float2bfloat16(x0 - __bfloat162float(h0));
    __nv_bfloat16 l1 = __float2bfloat16(x1 - __bfloat162float(h1));
    hi = (unsigned)__bfloat16_as_ushort(h0) | ((unsigned)__bfloat16_as_ushort(h1) << 16);
    lo = (unsigned)__bfloat16_as_ushort(l0) | ((unsigned)__bfloat16_as_ushort(l1) << 16);
}

__device__ __forceinline__ void mma_bf16(float d[4], const unsigned a[4], const unsigned b[2]) {
    asm volatile(
        "mma.sync.aligned.m16n8k16.row.col.f32.bf16.bf16.f32 "
        "{%0,%1,%2,%3}, {%4,%5,%6,%7}, {%8,%9}, {%0,%1,%2,%3};\n"
        : "+f"(d[0]), "+f"(d[1]), "+f"(d[2]), "+f"(d[3])
        : "r"(a[0]), "r"(a[1]), "r"(a[2]), "r"(a[3]), "r"(b[0]), "r"(b[1]));
}

// ---------------- kernels ----------------

__global__ void k_pnorm(const float* __restrict__ p1, const float* __restrict__ p2,
                        const float* __restrict__ p3, float* __restrict__ invn) {
    __shared__ float red[4];
    int tid = threadIdx.x;
    const float* ps[3] = {p1, p2, p3};
    for (int j = 0; j < 3; j++) {
        float v = ps[j][tid];
        float s = v * v;
#pragma unroll
        for (int o = 16; o > 0; o >>= 1) s += __shfl_down_sync(0xffffffffu, s, o);
        if ((tid & 31) == 0) red[tid >> 5] = s;
        __syncthreads();
        if (tid == 0) invn[j] = rsqrtf(red[0] + red[1] + red[2] + red[3]);
        __syncthreads();
    }
}

// GEMM (round-9 proven): 128x128 block tile, 8 warps, bf16x3, smem staged.
__global__ __launch_bounds__(256, 2) void k_gemm_tc(const float* __restrict__ X,
                                                    const float* __restrict__ W,
                                                    float* __restrict__ Y) {
    __shared__ uint2 Xs[128 * 12];
    __shared__ uint2 Ws[128 * 12];

    const int tid = threadIdx.x;
    const int lane = tid & 31;
    const int w = tid >> 5;
    const int g = lane >> 2;
    const int t4 = lane & 3;
    const int row0 = blockIdx.x * 128;
    const int mrow = w * 16;

    float d[16][4];
#pragma unroll
    for (int nt = 0; nt < 16; nt++)
#pragma unroll
        for (int j = 0; j < 4; j++) d[nt][j] = 0.f;

    const int xr = tid >> 1;
    const int xh = tid & 1;

    for (int kb = 0; kb < 128; kb += 16) {
        {
            const float* xrow = &X[(size_t)(row0 + xr) * 128 + kb + 8 * xh];
            float4 v1 = *(const float4*)&xrow[0];
            float4 v2 = *(const float4*)&xrow[4];
            unsigned h, l;
            split2(v1.x, v1.y, h, l); Xs[xr * 12 + 4 * xh + 0] = make_uint2(h, l);
            split2(v1.z, v1.w, h, l); Xs[xr * 12 + 4 * xh + 1] = make_uint2(h, l);
            split2(v2.x, v2.y, h, l); Xs[xr * 12 + 4 * xh + 2] = make_uint2(h, l);
            split2(v2.z, v2.w, h, l); Xs[xr * 12 + 4 * xh + 3] = make_uint2(h, l);
        }
        {
            int n = tid & 127, kh = tid >> 7;
#pragma unroll
            for (int j = 0; j < 4; j++) {
                int k = kb + 8 * kh + 2 * j;
                float w0 = W[(size_t)k * 128 + n];
                float w1 = W[(size_t)(k + 1) * 128 + n];
                unsigned h, l;
                split2(w0, w1, h, l);
                Ws[n * 12 + 4 * kh + j] = make_uint2(h, l);
            }
        }
        __syncthreads();
        {
            uint2 xa0 = Xs[(mrow + g) * 12 + t4];
            uint2 xa1 = Xs[(mrow + g + 8) * 12 + t4];
            uint2 xa2 = Xs[(mrow + g) * 12 + 4 + t4];
            uint2 xa3 = Xs[(mrow + g + 8) * 12 + 4 + t4];
            unsigned ahi[4] = {xa0.x, xa1.x, xa2.x, xa3.x};
            unsigned alo[4] = {xa0.y, xa1.y, xa2.y, xa3.y};
#pragma unroll
            for (int nt = 0; nt < 16; nt++) {
                uint2 wb0 = Ws[(nt * 8 + g) * 12 + t4];
                uint2 wb1 = Ws[(nt * 8 + g) * 12 + 4 + t4];
                unsigned bhi[2] = {wb0.x, wb1.x};
                unsigned blo[2] = {wb0.y, wb1.y};
                mma_bf16(d[nt], ahi, bhi);
                mma_bf16(d[nt], ahi, blo);
                mma_bf16(d[nt], alo, bhi);
            }
        }
        __syncthreads();
    }

#pragma unroll
    for (int nt = 0; nt < 16; nt++) {
        const int n0 = nt * 8;
        float* y0 = &Y[(size_t)(row0 + mrow + g) * 128 + n0 + 2 * t4];
        float* y1 = &Y[(size_t)(row0 + mrow + g + 8) * 128 + n0 + 2 * t4];
        *(float2*)y0 = make_float2(d[nt][0], d[nt][1]);
        *(float2*)y1 = make_float2(d[nt][2], d[nt][3]);
    }
}

// stage-1 CSR build from raw edges: 1 block/graph (n_per=512, all 2048 edges)
__global__ __launch_bounds__(512) void k_csr(const int* __restrict__ src,
                                             const int* __restrict__ dst,
                                             int* __restrict__ offs, int* __restrict__ endo,
                                             float* __restrict__ dinv, int* __restrict__ elist) {
    __shared__ int deg[512];
    __shared__ int scn[512];
    __shared__ int cur[512];
    int b = blockIdx.x, tid = threadIdx.x;
    int nbase = b * 512;
    int ebase = b * 2048;
    deg[tid] = 0;
    __syncthreads();
    for (int e = tid; e < 2048; e += 512)
        atomicAdd(&deg[dst[ebase + e] - nbase], 1);
    __syncthreads();
    int d = deg[tid];
    scn[tid] = d;
    __syncthreads();
#pragma unroll
    for (int off = 1; off < 512; off <<= 1) {
        int v = (tid >= off) ? scn[tid - off] : 0;
        __syncthreads();
        scn[tid] += v;
        __syncthreads();
    }
    int excl = scn[tid] - d;
    offs[nbase + tid] = ebase + excl;
    endo[nbase + tid] = ebase + excl + d;
    dinv[nbase + tid] = rsqrtf(1.0f + (float)d);
    cur[tid] = ebase + excl;
    __syncthreads();
    for (int e = tid; e < 2048; e += 512) {
        int dd = dst[ebase + e] - nbase;
        int pos = atomicAdd(&cur[dd], 1);
        elist[pos] = src[ebase + e];
    }
}

// fused: GCN aggregate (gather, unroll x2) + bias + ReLU + pool score. 1 warp/node.
__global__ __launch_bounds__(256) void k_node(const float* __restrict__ hW,
                                              const float* __restrict__ bias,
                                              const float* __restrict__ dinv,
                                              const int* __restrict__ offs,
                                              const int* __restrict__ endo,
                                              const int* __restrict__ elist,
                                              const float* __restrict__ p,
                                              const float* __restrict__ invn,
                                              float* __restrict__ h,
                                              float* __restrict__ score, int n) {
    __shared__ float ps[128];
    __shared__ float bs[128];
    int tid = threadIdx.x, lane = tid & 31, w = tid >> 5;
    if (tid < 128) { ps[tid] = p[tid]; bs[tid] = bias[tid]; }
    __syncthreads();
    int i = blockIdx.x * 8 + w;
    if (i >= n) return;
    float dii = dinv[i];
    float s2 = dii * dii;
    float4 acc = *(const float4*)&hW[(size_t)i * F + lane * 4];
    float4 bb = *(const float4*)&bs[lane * 4];
    acc.x = acc.x * s2 + bb.x; acc.y = acc.y * s2 + bb.y;
    acc.z = acc.z * s2 + bb.z; acc.w = acc.w * s2 + bb.w;
    float4 acc2 = make_float4(0.f, 0.f, 0.f, 0.f);
    int e = offs[i], ee = endo[i];
    for (; e + 1 < ee; e += 2) {
        int s0 = elist[e], s1 = elist[e + 1];
        float c0 = dinv[s0] * dii, c1 = dinv[s1] * dii;
        float4 v0 = *(const float4*)&hW[(size_t)s0 * F + lane * 4];
        float4 v1 = *(const float4*)&hW[(size_t)s1 * F + lane * 4];
        acc.x += v0.x * c0;  acc.y += v0.y * c0;
        acc.z += v0.z * c0;  acc.w += v0.w * c0;
        acc2.x += v1.x * c1; acc2.y += v1.y * c1;
        acc2.z += v1.z * c1; acc2.w += v1.w * c1;
    }
    if (e < ee) {
        int s0 = elist[e];
        float c0 = dinv[s0] * dii;
        float4 v0 = *(const float4*)&hW[(size_t)s0 * F + lane * 4];
        acc.x += v0.x * c0; acc.y += v0.y * c0;
        acc.z += v0.z * c0; acc.w += v0.w * c0;
    }
    acc.x += acc2.x; acc.y += acc2.y; acc.z += acc2.z; acc.w += acc2.w;
    acc.x = fmaxf(acc.x, 0.f); acc.y = fmaxf(acc.y, 0.f);
    acc.z = fmaxf(acc.z, 0.f); acc.w = fmaxf(acc.w, 0.f);
    *(float4*)&h[(size_t)i * F + lane * 4] = acc;
    float4 pv = *(const float4*)&ps[lane * 4];
    float d = acc.x * pv.x + acc.y * pv.y + acc.z * pv.z + acc.w * pv.w;
#pragma unroll
    for (int o = 16; o > 0; o >>= 1) d += __shfl_down_sync(0xffffffffu, d, o);
    if (lane == 0) score[i] = d * invn[0];
}

// fused pooling: top-k sort + gather/readout + relabel + NEXT-stage CSR.
// 1 block / graph, 512 threads. All per-graph state lives in smem.
__global__ __launch_bounds__(512) void k_pool(
    const float* __restrict__ score, int n_per, int k,
    const float* __restrict__ h, float* __restrict__ xk,
    float* __restrict__ z, int acc,
    const int* __restrict__ srcI, const int* __restrict__ dstI,
    const int* __restrict__ cntp,
    int* __restrict__ srcO, int* __restrict__ dstO, int* __restrict__ gcntO,
    int* __restrict__ offs, int* __restrict__ endo,
    float* __restrict__ dinv, int* __restrict__ elist,
    int do_relabel) {
    __shared__ float sc[512];
    __shared__ int   id[512];
    __shared__ int   nid[512];
    __shared__ int   perm_s[256];
    __shared__ float tanh_s[256];
    __shared__ float mxb[512], smb[512];
    __shared__ unsigned short esrc[2048], edst[2048];
    __shared__ int deg[256], cur[256];
    __shared__ int scnt;

    int b = blockIdx.x, tid = threadIdx.x;
    int nbase = b * n_per;

    // ---- top-k bitonic over 512 (pad -inf), (score desc, idx asc) ----
    sc[tid] = (tid < n_per) ? score[nbase + tid] : -INFINITY;
    id[tid] = tid;
    nid[tid] = -1;
    if (tid == 0) scnt = 0;
    __syncthreads();
    for (int kk = 2; kk <= 512; kk <<= 1) {
        for (int j = kk >> 1; j > 0; j >>= 1) {
            int ixj = tid ^ j;
            if (ixj > tid) {
                bool dir = ((tid & kk) == 0);
                float s1 = sc[tid], s2 = sc[ixj];
                int i1 = id[tid], i2 = id[ixj];
                bool swp = dir ? ((s2 > s1) || (s2 == s1 && i2 < i1))
                               : ((s1 > s2) || (s1 == s2 && i1 < i2));
                if (swp) { sc[tid] = s2; sc[ixj] = s1; id[tid] = i2; id[ixj] = i1; }
            }
            __syncthreads();
        }
    }
    if (tid < k) {
        int loc = id[tid];
        perm_s[tid] = loc;
        tanh_s[tid] = tanhf(sc[tid]);
        nid[loc] = tid;
    }
    __syncthreads();

    // ---- gather + readout: thread (jj = tid>>7, f = tid&127) ----
    {
        int f = tid & 127, jj = tid >> 7;
        float mx = -INFINITY, sm = 0.f;
        for (int j = jj; j < k; j += 4) {
            float v = h[(size_t)(nbase + perm_s[j]) * F + f] * tanh_s[j];
            if (xk) xk[(size_t)(b * k + j) * F + f] = v;
            mx = fmaxf(mx, v);
            sm += v;
        }
        mxb[tid] = mx; smb[tid] = sm;
        __syncthreads();
        if (tid < 128) {
            mx = fmaxf(fmaxf(mxb[tid], mxb[tid + 128]), fmaxf(mxb[tid + 256], mxb[tid + 384]));
            sm = (smb[tid] + smb[tid + 128] + smb[tid + 256] + smb[tid + 384]) * (1.0f / (float)k);
            if (acc) {
                z[b * 256 + tid] += mx;
                z[b * 256 + 128 + tid] += sm;
            } else {
                z[b * 256 + tid] = mx;
                z[b * 256 + 128 + tid] = sm;
            }
        }
    }
    if (!do_relabel) return;
    __syncthreads();

    // ---- relabel + compact into smem (and global for next stage) ----
    int ebase = b * 2048;
    int cnt = cntp ? cntp[b] : 2048;
    int bk = b * k;
    for (int e = tid; e < cnt; e += 512) {
        int ns = nid[srcI[ebase + e] - nbase];
        int nd = nid[dstI[ebase + e] - nbase];
        if (ns >= 0 && nd >= 0) {
            int pos = atomicAdd(&scnt, 1);
            esrc[pos] = (unsigned short)ns;
            edst[pos] = (unsigned short)nd;
            srcO[ebase + pos] = bk + ns;
            dstO[ebase + pos] = bk + nd;
        }
    }
    if (tid < k) deg[tid] = 0;
    __syncthreads();
    int ec = scnt;
    if (tid == 0) gcntO[b] = ec;
    for (int e = tid; e < ec; e += 512) atomicAdd(&deg[edst[e]], 1);
    __syncthreads();

    // ---- scan (reuse id as scratch) + CSR fill for next stage ----
    int d = (tid < k) ? deg[tid] : 0;
    id[tid] = d;
    __syncthreads();
#pragma unroll
    for (int off = 1; off < 512; off <<= 1) {
        int v = (tid >= off) ? id[tid - off] : 0;
        __syncthreads();
        id[tid] += v;
        __syncthreads();
    }
    if (tid < k) {
        int excl = id[tid] - d;
        offs[bk + tid] = ebase + excl;
        endo[bk + tid] = ebase + excl + d;
        dinv[bk + tid] = rsqrtf(1.0f + (float)d);
        cur[tid] = excl;
    }
    __syncthreads();
    for (int e = tid; e < ec; e += 512) {
        int pos = atomicAdd(&cur[edst[e]], 1);
        elist[ebase + pos] = bk + esrc[e];
    }
}

// final MLP + log_softmax
__global__ __launch_bounds__(128) void k_mlp(const float* __restrict__ z,
                      const float* __restrict__ L1, const float* __restrict__ bl1,
                      const float* __restrict__ L2, const float* __restrict__ bl2,
                      const float* __restrict__ L3, const float* __restrict__ bl3,
                      float* __restrict__ out) {
    __shared__ float zr[256];
    __shared__ float h1[128];
    __shared__ float h2[64];
    __shared__ float lg[2];
    int b = blockIdx.x, tid = threadIdx.x;
    zr[tid] = z[b * 256 + tid];
    zr[128 + tid] = z[b * 256 + 128 + tid];
    __syncthreads();
    float a = bl1[tid];
    for (int i = 0; i < 256; i++) a += zr[i] * L1[i * 128 + tid];
    h1[tid] = fmaxf(a, 0.f);
    __syncthreads();
    if (tid < 64) {
        float a2 = bl2[tid];
        for (int i = 0; i < 128; i++) a2 += h1[i] * L2[i * 64 + tid];
        h2[tid] = fmaxf(a2, 0.f);
    }
    __syncthreads();
    if (tid < 2) {
        float a3 = bl3[tid];
        for (int i = 0; i < 64; i++) a3 += h2[i] * L3[i * 2 + tid];
        lg[tid] = a3;
    }
    __syncthreads();
    if (tid == 0) {
        float m = fmaxf(lg[0], lg[1]);
        float lse = m + logf(expf(lg[0] - m) + expf(lg[1] - m));
        out[b * 2 + 0] = lg[0] - lse;
        out[b * 2 + 1] = lg[1] - lse;
    }
}

// ---------------- host orchestration ----------------
extern "C" void kernel_launch(void* const* d_in, const int* in_sizes, int n_in,
                              void* d_out, int out_size) {
    const float* x   = (const float*)d_in[0];
    const int*   src = (const int*)d_in[1];
    const int*   dst = (const int*)d_in[2];
    const float* W1 = (const float*)d_in[3];  const float* b1 = (const float*)d_in[4];
    const float* W2 = (const float*)d_in[5];  const float* b2 = (const float*)d_in[6];
    const float* W3 = (const float*)d_in[7];  const float* b3 = (const float*)d_in[8];
    const float* p1 = (const float*)d_in[9];
    const float* p2 = (const float*)d_in[10];
    const float* p3 = (const float*)d_in[11];
    const float* L1 = (const float*)d_in[12]; const float* bl1 = (const float*)d_in[13];
    const float* L2 = (const float*)d_in[14]; const float* bl2 = (const float*)d_in[15];
    const float* L3 = (const float*)d_in[16]; const float* bl3 = (const float*)d_in[17];
    float* out = (float*)d_out;

    float *A, *B, *dinv, *score, *z, *invn;
    int *offs, *endo, *elist;
    int *srcA, *dstA, *srcB, *dstB, *gcnt2, *gcnt3;
    cudaGetSymbolAddress((void**)&A, g_bufA);
    cudaGetSymbolAddress((void**)&B, g_bufB);
    cudaGetSymbolAddress((void**)&dinv, g_dinv);
    cudaGetSymbolAddress((void**)&score, g_score);
    cudaGetSymbolAddress((void**)&offs, g_offs);
    cudaGetSymbolAddress((void**)&endo, g_endo);
    cudaGetSymbolAddress((void**)&elist, g_elist);
    cudaGetSymbolAddress((void**)&srcA, g_srcA);
    cudaGetSymbolAddress((void**)&dstA, g_dstA);
    cudaGetSymbolAddress((void**)&srcB, g_srcB);
    cudaGetSymbolAddress((void**)&dstB, g_dstB);
    cudaGetSymbolAddress((void**)&gcnt2, g_gcnt2);
    cudaGetSymbolAddress((void**)&gcnt3, g_gcnt3);
    cudaGetSymbolAddress((void**)&z, g_z);
    cudaGetSymbolAddress((void**)&invn, g_invn);

    // ---------- stage 1: n=65536, n_per=512, k=256 ----------
    {
        const int n = 65536, n_per = 512, k = 256;
        k_pnorm<<<1, 128>>>(p1, p2, p3, invn);
        k_gemm_tc<<<n / 128, 256>>>(x, W1, A);
        k_csr<<<BATCH, 512>>>(src, dst, offs, endo, dinv, elist);
        k_node<<<n / 8, 256>>>(A, b1, dinv, offs, endo, elist, p1, invn + 0, B, score, n);
        k_pool<<<BATCH, 512>>>(score, n_per, k, B, A, z, 0,
                               src, dst, nullptr,
                               srcA, dstA, gcnt2,
                               offs, endo, dinv, elist, 1);
    }
    // ---------- stage 2: n=32768, n_per=256, k=128 ----------
    {
        const int n = 32768, n_per = 256, k = 128;
        k_gemm_tc<<<n / 128, 256>>>(A, W2, B);
        k_node<<<n / 8, 256>>>(B, b2, dinv, offs, endo, elist, p2, invn + 1, A, score, n);
        k_pool<<<BATCH, 512>>>(score, n_per, k, A, B, z, 1,
                               srcA, dstA, gcnt2,
                               srcB, dstB, gcnt3,
                               offs, endo, dinv, elist, 1);
    }
    // ---------- stage 3: n=16384, n_per=128, k=64 ----------
    {
        const int n = 16384, n_per = 128, k = 64;
        k_gemm_tc<<<n / 128, 256>>>(B, W3, A);
        k_node<<<n / 8, 256>>>(A, b3, dinv, offs, endo, elist, p3, invn + 2, B, score, n);
        k_pool<<<BATCH, 512>>>(score, n_per, k, B, nullptr, z, 1,
                               nullptr, nullptr, nullptr,
                               nullptr, nullptr, nullptr,
                               nullptr, nullptr, nullptr, nullptr, 0);
    }
    // ---------- MLP head ----------
    k_mlp<<<BATCH, 128>>>(z, L1, bl1, L2, bl2, L3, bl3, out);
}

// round 15
// speedup vs baseline: 1.3958x; 1.0014x over previous
#include <cuda_runtime.h>
#include <cuda_bf16.h>
#include <cstdint>
#include <stdint.h>
#include <math.h>

#define BATCH   128
#define N0      512
#define E_TOT   262144
#define F       128
#define NMAX    65536

// ---------------- static scratch ----------------
__device__ float g_bufA[NMAX * F];
__device__ float g_bufB[NMAX * F];
__device__ float g_dinv[NMAX];
__device__ float g_score[NMAX];
__device__ int   g_offs[NMAX];
__device__ int   g_endo[NMAX];
__device__ int   g_elist[E_TOT];
__device__ int   g_srcA[E_TOT], g_dstA[E_TOT];
__device__ int   g_srcB[E_TOT], g_dstB[E_TOT];
__device__ int   g_gcnt2[BATCH], g_gcnt3[BATCH];
__device__ float g_z[BATCH * 2 * F];
__device__ float g_invn[3];

// ---------------- helpers ----------------
__device__ __forceinline__ void split2(float x0, float x1, unsigned& hi, unsigned& lo) {
    __nv_bfloat16 h0 = __float2bfloat16(x0);
    __nv_bfloat16 h1 = __float2bfloat16(x1);
    __nv_bfloat16 l0 = __float2bfloat16(x0 - __bfloat162float(h0));
    __nv_bfloat16 l1 = __float2bfloat16(x1 - __bfloat162float(h1));
    hi = (unsigned)__bfloat16_as_ushort(h0) | ((unsigned)__bfloat16_as_ushort(h1) << 16);
    lo = (unsigned)__bfloat16_as_ushort(l0) | ((unsigned)__bfloat16_as_ushort(l1) << 16);
}

__device__ __forceinline__ void mma_bf16(float d[4], const unsigned a[4], const unsigned b[2]) {
    asm volatile(
        "mma.sync.aligned.m16n8k16.row.col.f32.bf16.bf16.f32 "
        "{%0,%1,%2,%3}, {%4,%5,%6,%7}, {%8,%9}, {%0,%1,%2,%3};\n"
        : "+f"(d[0]), "+f"(d[1]), "+f"(d[2]), "+f"(d[3])
        : "r"(a[0]), "r"(a[1]), "r"(a[2]), "r"(a[3]), "r"(b[0]), "r"(b[1]));
}

// ---------------- kernels ----------------

__global__ void k_pnorm(const float* __restrict__ p1, const float* __restrict__ p2,
                        const float* __restrict__ p3, float* __restrict__ invn) {
    __shared__ float red[4];
    int tid = threadIdx.x;
    const float* ps[3] = {p1, p2, p3};
    for (int j = 0; j < 3; j++) {
        float v = ps[j][tid];
        float s = v * v;
#pragma unroll
        for (int o = 16; o > 0; o >>= 1) s += __shfl_down_sync(0xffffffffu, s, o);
        if ((tid & 31) == 0) red[tid >> 5] = s;
        __syncthreads();
        if (tid == 0) invn[j] = rsqrtf(red[0] + red[1] + red[2] + red[3]);
        __syncthreads();
    }
}

// GEMM (round-9 proven): 128x128 block tile, 8 warps, bf16x3, smem staged.
__global__ __launch_bounds__(256, 2) void k_gemm_tc(const float* __restrict__ X,
                                                    const float* __restrict__ W,
                                                    float* __restrict__ Y) {
    __shared__ uint2 Xs[128 * 12];
    __shared__ uint2 Ws[128 * 12];

    const int tid = threadIdx.x;
    const int lane = tid & 31;
    const int w = tid >> 5;
    const int g = lane >> 2;
    const int t4 = lane & 3;
    const int row0 = blockIdx.x * 128;
    const int mrow = w * 16;

    float d[16][4];
#pragma unroll
    for (int nt = 0; nt < 16; nt++)
#pragma unroll
        for (int j = 0; j < 4; j++) d[nt][j] = 0.f;

    const int xr = tid >> 1;
    const int xh = tid & 1;

    for (int kb = 0; kb < 128; kb += 16) {
        {
            const float* xrow = &X[(size_t)(row0 + xr) * 128 + kb + 8 * xh];
            float4 v1 = *(const float4*)&xrow[0];
            float4 v2 = *(const float4*)&xrow[4];
            unsigned h, l;
            split2(v1.x, v1.y, h, l); Xs[xr * 12 + 4 * xh + 0] = make_uint2(h, l);
            split2(v1.z, v1.w, h, l); Xs[xr * 12 + 4 * xh + 1] = make_uint2(h, l);
            split2(v2.x, v2.y, h, l); Xs[xr * 12 + 4 * xh + 2] = make_uint2(h, l);
            split2(v2.z, v2.w, h, l); Xs[xr * 12 + 4 * xh + 3] = make_uint2(h, l);
        }
        {
            int n = tid & 127, kh = tid >> 7;
#pragma unroll
            for (int j = 0; j < 4; j++) {
                int k = kb + 8 * kh + 2 * j;
                float w0 = W[(size_t)k * 128 + n];
                float w1 = W[(size_t)(k + 1) * 128 + n];
                unsigned h, l;
                split2(w0, w1, h, l);
                Ws[n * 12 + 4 * kh + j] = make_uint2(h, l);
            }
        }
        __syncthreads();
        {
            uint2 xa0 = Xs[(mrow + g) * 12 + t4];
            uint2 xa1 = Xs[(mrow + g + 8) * 12 + t4];
            uint2 xa2 = Xs[(mrow + g) * 12 + 4 + t4];
            uint2 xa3 = Xs[(mrow + g + 8) * 12 + 4 + t4];
            unsigned ahi[4] = {xa0.x, xa1.x, xa2.x, xa3.x};
            unsigned alo[4] = {xa0.y, xa1.y, xa2.y, xa3.y};
#pragma unroll
            for (int nt = 0; nt < 16; nt++) {
                uint2 wb0 = Ws[(nt * 8 + g) * 12 + t4];
                uint2 wb1 = Ws[(nt * 8 + g) * 12 + 4 + t4];
                unsigned bhi[2] = {wb0.x, wb1.x};
                unsigned blo[2] = {wb0.y, wb1.y};
                mma_bf16(d[nt], ahi, bhi);
                mma_bf16(d[nt], ahi, blo);
                mma_bf16(d[nt], alo, bhi);
            }
        }
        __syncthreads();
    }

#pragma unroll
    for (int nt = 0; nt < 16; nt++) {
        const int n0 = nt * 8;
        float* y0 = &Y[(size_t)(row0 + mrow + g) * 128 + n0 + 2 * t4];
        float* y1 = &Y[(size_t)(row0 + mrow + g + 8) * 128 + n0 + 2 * t4];
        *(float2*)y0 = make_float2(d[nt][0], d[nt][1]);
        *(float2*)y1 = make_float2(d[nt][2], d[nt][3]);
    }
}

// stage-1 CSR build from raw edges: 1 block/graph (n_per=512, all 2048 edges)
__global__ __launch_bounds__(512) void k_csr(const int* __restrict__ src,
                                             const int* __restrict__ dst,
                                             int* __restrict__ offs, int* __restrict__ endo,
                                             float* __restrict__ dinv, int* __restrict__ elist) {
    __shared__ int deg[512];
    __shared__ int scn[512];
    __shared__ int cur[512];
    int b = blockIdx.x, tid = threadIdx.x;
    int nbase = b * 512;
    int ebase = b * 2048;
    deg[tid] = 0;
    __syncthreads();
    for (int e = tid; e < 2048; e += 512)
        atomicAdd(&deg[dst[ebase + e] - nbase], 1);
    __syncthreads();
    int d = deg[tid];
    scn[tid] = d;
    __syncthreads();
#pragma unroll
    for (int off = 1; off < 512; off <<= 1) {
        int v = (tid >= off) ? scn[tid - off] : 0;
        __syncthreads();
        scn[tid] += v;
        __syncthreads();
    }
    int excl = scn[tid] - d;
    offs[nbase + tid] = ebase + excl;
    endo[nbase + tid] = ebase + excl + d;
    dinv[nbase + tid] = rsqrtf(1.0f + (float)d);
    cur[tid] = ebase + excl;
    __syncthreads();
    for (int e = tid; e < 2048; e += 512) {
        int dd = dst[ebase + e] - nbase;
        int pos = atomicAdd(&cur[dd], 1);
        elist[pos] = src[ebase + e];
    }
}

// fused: GCN aggregate + bias + ReLU + pool score. 1 warp/node.
// Warp-parallel prefetch of neighbor indices + dinv kills the pointer-chase.
__global__ __launch_bounds__(256) void k_node(const float* __restrict__ hW,
                                              const float* __restrict__ bias,
                                              const float* __restrict__ dinv,
                                              const int* __restrict__ offs,
                                              const int* __restrict__ endo,
                                              const int* __restrict__ elist,
                                              const float* __restrict__ p,
                                              const float* __restrict__ invn,
                                              float* __restrict__ h,
                                              float* __restrict__ score, int n) {
    __shared__ float ps[128];
    __shared__ float bs[128];
    int tid = threadIdx.x, lane = tid & 31, w = tid >> 5;
    if (tid < 128) { ps[tid] = p[tid]; bs[tid] = bias[tid]; }
    __syncthreads();
    int i = blockIdx.x * 8 + w;
    if (i >= n) return;
    float dii = dinv[i];
    float s2 = dii * dii;
    float4 acc = *(const float4*)&hW[(size_t)i * F + lane * 4];
    float4 bb = *(const float4*)&bs[lane * 4];
    acc.x = acc.x * s2 + bb.x; acc.y = acc.y * s2 + bb.y;
    acc.z = acc.z * s2 + bb.z; acc.w = acc.w * s2 + bb.w;
    float4 acc2 = make_float4(0.f, 0.f, 0.f, 0.f);

    int e0 = offs[i], ee = endo[i];
    for (int base = e0; base < ee; base += 32) {
        int cnt = min(32, ee - base);
        // cooperative prefetch: 1 coalesced elist load + 1 gathered dinv load
        int sIdx = 0;
        float sdv = 0.f;
        if (lane < cnt) {
            sIdx = elist[base + lane];
            sdv = dinv[sIdx];
        }
        int j = 0;
        for (; j + 1 < cnt; j += 2) {
            int s0 = __shfl_sync(0xffffffffu, sIdx, j);
            int s1 = __shfl_sync(0xffffffffu, sIdx, j + 1);
            float c0 = __shfl_sync(0xffffffffu, sdv, j) * dii;
            float c1 = __shfl_sync(0xffffffffu, sdv, j + 1) * dii;
            float4 v0 = *(const float4*)&hW[(size_t)s0 * F + lane * 4];
            float4 v1 = *(const float4*)&hW[(size_t)s1 * F + lane * 4];
            acc.x += v0.x * c0;  acc.y += v0.y * c0;
            acc.z += v0.z * c0;  acc.w += v0.w * c0;
            acc2.x += v1.x * c1; acc2.y += v1.y * c1;
            acc2.z += v1.z * c1; acc2.w += v1.w * c1;
        }
        if (j < cnt) {
            int s0 = __shfl_sync(0xffffffffu, sIdx, j);
            float c0 = __shfl_sync(0xffffffffu, sdv, j) * dii;
            float4 v0 = *(const float4*)&hW[(size_t)s0 * F + lane * 4];
            acc.x += v0.x * c0; acc.y += v0.y * c0;
            acc.z += v0.z * c0; acc.w += v0.w * c0;
        }
    }
    acc.x += acc2.x; acc.y += acc2.y; acc.z += acc2.z; acc.w += acc2.w;
    acc.x = fmaxf(acc.x, 0.f); acc.y = fmaxf(acc.y, 0.f);
    acc.z = fmaxf(acc.z, 0.f); acc.w = fmaxf(acc.w, 0.f);
    *(float4*)&h[(size_t)i * F + lane * 4] = acc;
    float4 pv = *(const float4*)&ps[lane * 4];
    float d = acc.x * pv.x + acc.y * pv.y + acc.z * pv.z + acc.w * pv.w;
#pragma unroll
    for (int o = 16; o > 0; o >>= 1) d += __shfl_down_sync(0xffffffffu, d, o);
    if (lane == 0) score[i] = d * invn[0];
}

// fused pooling: top-k sort + gather/readout + relabel + NEXT-stage CSR.
__global__ __launch_bounds__(512) void k_pool(
    const float* __restrict__ score, int n_per, int k,
    const float* __restrict__ h, float* __restrict__ xk,
    float* __restrict__ z, int acc,
    const int* __restrict__ srcI, const int* __restrict__ dstI,
    const int* __restrict__ cntp,
    int* __restrict__ srcO, int* __restrict__ dstO, int* __restrict__ gcntO,
    int* __restrict__ offs, int* __restrict__ endo,
    float* __restrict__ dinv, int* __restrict__ elist,
    int do_relabel) {
    __shared__ float sc[512];
    __shared__ int   id[512];
    __shared__ int   nid[512];
    __shared__ int   perm_s[256];
    __shared__ float tanh_s[256];
    __shared__ float mxb[512], smb[512];
    __shared__ unsigned short esrc[2048], edst[2048];
    __shared__ int deg[256], cur[256];
    __shared__ int scnt;

    int b = blockIdx.x, tid = threadIdx.x;
    int nbase = b * n_per;

    sc[tid] = (tid < n_per) ? score[nbase + tid] : -INFINITY;
    id[tid] = tid;
    nid[tid] = -1;
    if (tid == 0) scnt = 0;
    __syncthreads();
    for (int kk = 2; kk <= 512; kk <<= 1) {
        for (int j = kk >> 1; j > 0; j >>= 1) {
            int ixj = tid ^ j;
            if (ixj > tid) {
                bool dir = ((tid & kk) == 0);
                float s1 = sc[tid], s2 = sc[ixj];
                int i1 = id[tid], i2 = id[ixj];
                bool swp = dir ? ((s2 > s1) || (s2 == s1 && i2 < i1))
                               : ((s1 > s2) || (s1 == s2 && i1 < i2));
                if (swp) { sc[tid] = s2; sc[ixj] = s1; id[tid] = i2; id[ixj] = i1; }
            }
            __syncthreads();
        }
    }
    if (tid < k) {
        int loc = id[tid];
        perm_s[tid] = loc;
        tanh_s[tid] = tanhf(sc[tid]);
        nid[loc] = tid;
    }
    __syncthreads();

    {
        int f = tid & 127, jj = tid >> 7;
        float mx = -INFINITY, sm = 0.f;
        for (int j = jj; j < k; j += 4) {
            float v = h[(size_t)(nbase + perm_s[j]) * F + f] * tanh_s[j];
            if (xk) xk[(size_t)(b * k + j) * F + f] = v;
            mx = fmaxf(mx, v);
            sm += v;
        }
        mxb[tid] = mx; smb[tid] = sm;
        __syncthreads();
        if (tid < 128) {
            mx = fmaxf(fmaxf(mxb[tid], mxb[tid + 128]), fmaxf(mxb[tid + 256], mxb[tid + 384]));
            sm = (smb[tid] + smb[tid + 128] + smb[tid + 256] + smb[tid + 384]) * (1.0f / (float)k);
            if (acc) {
                z[b * 256 + tid] += mx;
                z[b * 256 + 128 + tid] += sm;
            } else {
                z[b * 256 + tid] = mx;
                z[b * 256 + 128 + tid] = sm;
            }
        }
    }
    if (!do_relabel) return;
    __syncthreads();

    int ebase = b * 2048;
    int cnt = cntp ? cntp[b] : 2048;
    int bk = b * k;
    for (int e = tid; e < cnt; e += 512) {
        int ns = nid[srcI[ebase + e] - nbase];
        int nd = nid[dstI[ebase + e] - nbase];
        if (ns >= 0 && nd >= 0) {
            int pos = atomicAdd(&scnt, 1);
            esrc[pos] = (unsigned short)ns;
            edst[pos] = (unsigned short)nd;
            srcO[ebase + pos] = bk + ns;
            dstO[ebase + pos] = bk + nd;
        }
    }
    if (tid < k) deg[tid] = 0;
    __syncthreads();
    int ec = scnt;
    if (tid == 0) gcntO[b] = ec;
    for (int e = tid; e < ec; e += 512) atomicAdd(&deg[edst[e]], 1);
    __syncthreads();

    int d = (tid < k) ? deg[tid] : 0;
    id[tid] = d;
    __syncthreads();
#pragma unroll
    for (int off = 1; off < 512; off <<= 1) {
        int v = (tid >= off) ? id[tid - off] : 0;
        __syncthreads();
        id[tid] += v;
        __syncthreads();
    }
    if (tid < k) {
        int excl = id[tid] - d;
        offs[bk + tid] = ebase + excl;
        endo[bk + tid] = ebase + excl + d;
        dinv[bk + tid] = rsqrtf(1.0f + (float)d);
        cur[tid] = excl;
    }
    __syncthreads();
    for (int e = tid; e < ec; e += 512) {
        int pos = atomicAdd(&cur[edst[e]], 1);
        elist[ebase + pos] = bk + esrc[e];
    }
}

// final MLP + log_softmax
__global__ __launch_bounds__(128) void k_mlp(const float* __restrict__ z,
                      const float* __restrict__ L1, const float* __restrict__ bl1,
                      const float* __restrict__ L2, const float* __restrict__ bl2,
                      const float* __restrict__ L3, const float* __restrict__ bl3,
                      float* __restrict__ out) {
    __shared__ float zr[256];
    __shared__ float h1[128];
    __shared__ float h2[64];
    __shared__ float lg[2];
    int b = blockIdx.x, tid = threadIdx.x;
    zr[tid] = z[b * 256 + tid];
    zr[128 + tid] = z[b * 256 + 128 + tid];
    __syncthreads();
    float a = bl1[tid];
    for (int i = 0; i < 256; i++) a += zr[i] * L1[i * 128 + tid];
    h1[tid] = fmaxf(a, 0.f);
    __syncthreads();
    if (tid < 64) {
        float a2 = bl2[tid];
        for (int i = 0; i < 128; i++) a2 += h1[i] * L2[i * 64 + tid];
        h2[tid] = fmaxf(a2, 0.f);
    }
    __syncthreads();
    if (tid < 2) {
        float a3 = bl3[tid];
        for (int i = 0; i < 64; i++) a3 += h2[i] * L3[i * 2 + tid];
        lg[tid] = a3;
    }
    __syncthreads();
    if (tid == 0) {
        float m = fmaxf(lg[0], lg[1]);
        float lse = m + logf(expf(lg[0] - m) + expf(lg[1] - m));
        out[b * 2 + 0] = lg[0] - lse;
        out[b * 2 + 1] = lg[1] - lse;
    }
}

// ---------------- host orchestration ----------------
extern "C" void kernel_launch(void* const* d_in, const int* in_sizes, int n_in,
                              void* d_out, int out_size) {
    const float* x   = (const float*)d_in[0];
    const int*   src = (const int*)d_in[1];
    const int*   dst = (const int*)d_in[2];
    const float* W1 = (const float*)d_in[3];  const float* b1 = (const float*)d_in[4];
    const float* W2 = (const float*)d_in[5];  const float* b2 = (const float*)d_in[6];
    const float* W3 = (const float*)d_in[7];  const float* b3 = (const float*)d_in[8];
    const float* p1 = (const float*)d_in[9];
    const float* p2 = (const float*)d_in[10];
    const float* p3 = (const float*)d_in[11];
    const float* L1 = (const float*)d_in[12]; const float* bl1 = (const float*)d_in[13];
    const float* L2 = (const float*)d_in[14]; const float* bl2 = (const float*)d_in[15];
    const float* L3 = (const float*)d_in[16]; const float* bl3 = (const float*)d_in[17];
    float* out = (float*)d_out;

    float *A, *B, *dinv, *score, *z, *invn;
    int *offs, *endo, *elist;
    int *srcA, *dstA, *srcB, *dstB, *gcnt2, *gcnt3;
    cudaGetSymbolAddress((void**)&A, g_bufA);
    cudaGetSymbolAddress((void**)&B, g_bufB);
    cudaGetSymbolAddress((void**)&dinv, g_dinv);
    cudaGetSymbolAddress((void**)&score, g_score);
    cudaGetSymbolAddress((void**)&offs, g_offs);
    cudaGetSymbolAddress((void**)&endo, g_endo);
    cudaGetSymbolAddress((void**)&elist, g_elist);
    cudaGetSymbolAddress((void**)&srcA, g_srcA);
    cudaGetSymbolAddress((void**)&dstA, g_dstA);
    cudaGetSymbolAddress((void**)&srcB, g_srcB);
    cudaGetSymbolAddress((void**)&dstB, g_dstB);
    cudaGetSymbolAddress((void**)&gcnt2, g_gcnt2);
    cudaGetSymbolAddress((void**)&gcnt3, g_gcnt3);
    cudaGetSymbolAddress((void**)&z, g_z);
    cudaGetSymbolAddress((void**)&invn, g_invn);

    // ---------- stage 1: n=65536, n_per=512, k=256 ----------
    {
        const int n = 65536, n_per = 512, k = 256;
        k_pnorm<<<1, 128>>>(p1, p2, p3, invn);
        k_gemm_tc<<<n / 128, 256>>>(x, W1, A);
        k_csr<<<BATCH, 512>>>(src, dst, offs, endo, dinv, elist);
        k_node<<<n / 8, 256>>>(A, b1, dinv, offs, endo, elist, p1, invn + 0, B, score, n); // ncu slot 5
        k_pool<<<BATCH, 512>>>(score, n_per, k, B, A, z, 0,
                               src, dst, nullptr,
                               srcA, dstA, gcnt2,
                               offs, endo, dinv, elist, 1);
    }
    // ---------- stage 2: n=32768, n_per=256, k=128 ----------
    {
        const int n = 32768, n_per = 256, k = 128;
        k_gemm_tc<<<n / 128, 256>>>(A, W2, B);
        k_node<<<n / 8, 256>>>(B, b2, dinv, offs, endo, elist, p2, invn + 1, A, score, n);
        k_pool<<<BATCH, 512>>>(score, n_per, k, A, B, z, 1,
                               srcA, dstA, gcnt2,
                               srcB, dstB, gcnt3,
                               offs, endo, dinv, elist, 1);
    }
    // ---------- stage 3: n=16384, n_per=128, k=64 ----------
    {
        const int n = 16384, n_per = 128, k = 64;
        k_gemm_tc<<<n / 128, 256>>>(B, W3, A);
        k_node<<<n / 8, 256>>>(A, b3, dinv, offs, endo, elist, p3, invn + 2, B, score, n);
        k_pool<<<BATCH, 512>>>(score, n_per, k, B, nullptr, z, 1,
                               nullptr, nullptr, nullptr,
                               nullptr, nullptr, nullptr,
                               nullptr, nullptr, nullptr, nullptr, 0);
    }
    // ---------- MLP head ----------
    k_mlp<<<BATCH, 128>>>(z, L1, bl1, L2, bl2, L3, bl3, out);
}

// round 16
// speedup vs baseline: 1.5356x; 1.1002x over previous
#include <cuda_runtime.h>
#include <cuda_bf16.h>
#include <cstdint>
#include <stdint.h>
#include <math.h>

#define BATCH   128
#define N0      512
#define E_TOT   262144
#define F       128
#define NMAX    65536

// ---------------- static scratch ----------------
__device__ float g_bufA[NMAX * F];
__device__ float g_bufB[NMAX * F];
__device__ float g_dinv[NMAX];
__device__ float g_score[NMAX];
__device__ int   g_nid[NMAX];
__device__ int   g_offs[NMAX];
__device__ int   g_endo[NMAX];
__device__ int   g_elist[E_TOT];
__device__ int   g_srcA[E_TOT], g_dstA[E_TOT];
__device__ int   g_srcB[E_TOT], g_dstB[E_TOT];
__device__ int   g_gcnt2[BATCH], g_gcnt3[BATCH];
__device__ float g_z[BATCH * 2 * F];
__device__ float g_invn[3];

// ---------------- helpers ----------------
__device__ __forceinline__ void split2(float x0, float x1, unsigned& hi, unsigned& lo) {
    __nv_bfloat16 h0 = __float2bfloat16(x0);
    __nv_bfloat16 h1 = __float2bfloat16(x1);
    __nv_bfloat16 l0 = __float2bfloat16(x0 - __bfloat162float(h0));
    __nv_bfloat16 l1 = __float2bfloat16(x1 - __bfloat162float(h1));
    hi = (unsigned)__bfloat16_as_ushort(h0) | ((unsigned)__bfloat16_as_ushort(h1) << 16);
    lo = (unsigned)__bfloat16_as_ushort(l0) | ((unsigned)__bfloat16_as_ushort(l1) << 16);
}

__device__ __forceinline__ void mma_bf16(float d[4], const unsigned a[4], const unsigned b[2]) {
    asm volatile(
        "mma.sync.aligned.m16n8k16.row.col.f32.bf16.bf16.f32 "
        "{%0,%1,%2,%3}, {%4,%5,%6,%7}, {%8,%9}, {%0,%1,%2,%3};\n"
        : "+f"(d[0]), "+f"(d[1]), "+f"(d[2]), "+f"(d[3])
        : "r"(a[0]), "r"(a[1]), "r"(a[2]), "r"(a[3]), "r"(b[0]), "r"(b[1]));
}

// ---------------- kernels ----------------

// GEMM (proven): 128x128 block tile, 8 warps, bf16x3, smem staged.
__global__ __launch_bounds__(256, 2) void k_gemm_tc(const float* __restrict__ X,
                                                    const float* __restrict__ W,
                                                    float* __restrict__ Y) {
    __shared__ uint2 Xs[128 * 12];
    __shared__ uint2 Ws[128 * 12];

    const int tid = threadIdx.x;
    const int lane = tid & 31;
    const int w = tid >> 5;
    const int g = lane >> 2;
    const int t4 = lane & 3;
    const int row0 = blockIdx.x * 128;
    const int mrow = w * 16;

    float d[16][4];
#pragma unroll
    for (int nt = 0; nt < 16; nt++)
#pragma unroll
        for (int j = 0; j < 4; j++) d[nt][j] = 0.f;

    const int xr = tid >> 1;
    const int xh = tid & 1;

    for (int kb = 0; kb < 128; kb += 16) {
        {
            const float* xrow = &X[(size_t)(row0 + xr) * 128 + kb + 8 * xh];
            float4 v1 = *(const float4*)&xrow[0];
            float4 v2 = *(const float4*)&xrow[4];
            unsigned h, l;
            split2(v1.x, v1.y, h, l); Xs[xr * 12 + 4 * xh + 0] = make_uint2(h, l);
            split2(v1.z, v1.w, h, l); Xs[xr * 12 + 4 * xh + 1] = make_uint2(h, l);
            split2(v2.x, v2.y, h, l); Xs[xr * 12 + 4 * xh + 2] = make_uint2(h, l);
            split2(v2.z, v2.w, h, l); Xs[xr * 12 + 4 * xh + 3] = make_uint2(h, l);
        }
        {
            int n = tid & 127, kh = tid >> 7;
#pragma unroll
            for (int j = 0; j < 4; j++) {
                int k = kb + 8 * kh + 2 * j;
                float w0 = W[(size_t)k * 128 + n];
                float w1 = W[(size_t)(k + 1) * 128 + n];
                unsigned h, l;
                split2(w0, w1, h, l);
                Ws[n * 12 + 4 * kh + j] = make_uint2(h, l);
            }
        }
        __syncthreads();
        {
            uint2 xa0 = Xs[(mrow + g) * 12 + t4];
            uint2 xa1 = Xs[(mrow + g + 8) * 12 + t4];
            uint2 xa2 = Xs[(mrow + g) * 12 + 4 + t4];
            uint2 xa3 = Xs[(mrow + g + 8) * 12 + 4 + t4];
            unsigned ahi[4] = {xa0.x, xa1.x, xa2.x, xa3.x};
            unsigned alo[4] = {xa0.y, xa1.y, xa2.y, xa3.y};
#pragma unroll
            for (int nt = 0; nt < 16; nt++) {
                uint2 wb0 = Ws[(nt * 8 + g) * 12 + t4];
                uint2 wb1 = Ws[(nt * 8 + g) * 12 + 4 + t4];
                unsigned bhi[2] = {wb0.x, wb1.x};
                unsigned blo[2] = {wb0.y, wb1.y};
                mma_bf16(d[nt], ahi, bhi);
                mma_bf16(d[nt], ahi, blo);
                mma_bf16(d[nt], alo, bhi);
            }
        }
        __syncthreads();
    }

#pragma unroll
    for (int nt = 0; nt < 16; nt++) {
        const int n0 = nt * 8;
        float* y0 = &Y[(size_t)(row0 + mrow + g) * 128 + n0 + 2 * t4];
        float* y1 = &Y[(size_t)(row0 + mrow + g + 8) * 128 + n0 + 2 * t4];
        *(float2*)y0 = make_float2(d[nt][0], d[nt][1]);
        *(float2*)y1 = make_float2(d[nt][2], d[nt][3]);
    }
}

// stage-1 CSR from raw edges (1 block/graph) + fused pnorm (block 0, warps 0-2)
__global__ __launch_bounds__(512) void k_csr(const int* __restrict__ src,
                                             const int* __restrict__ dst,
                                             int* __restrict__ offs, int* __restrict__ endo,
                                             float* __restrict__ dinv, int* __restrict__ elist,
                                             const float* __restrict__ p1,
                                             const float* __restrict__ p2,
                                             const float* __restrict__ p3,
                                             float* __restrict__ invn) {
    __shared__ int deg[512];
    __shared__ int scn[512];
    __shared__ int cur[512];
    int b = blockIdx.x, tid = threadIdx.x;
    int lane = tid & 31, wid = tid >> 5;
    if (b == 0 && wid < 3) {   // fused pnorm: warp w computes ||p_w||^-1
        const float* pp = (wid == 0) ? p1 : ((wid == 1) ? p2 : p3);
        float s = 0.f;
        for (int q = lane; q < 128; q += 32) { float v = pp[q]; s += v * v; }
#pragma unroll
        for (int o = 16; o > 0; o >>= 1) s += __shfl_down_sync(0xffffffffu, s, o);
        if (lane == 0) invn[wid] = rsqrtf(s);
    }
    int nbase = b * 512;
    int ebase = b * 2048;
    deg[tid] = 0;
    __syncthreads();
    for (int e = tid; e < 2048; e += 512)
        atomicAdd(&deg[dst[ebase + e] - nbase], 1);
    __syncthreads();
    int d = deg[tid];
    scn[tid] = d;
    __syncthreads();
#pragma unroll
    for (int off = 1; off < 512; off <<= 1) {
        int v = (tid >= off) ? scn[tid - off] : 0;
        __syncthreads();
        scn[tid] += v;
        __syncthreads();
    }
    int excl = scn[tid] - d;
    offs[nbase + tid] = ebase + excl;
    endo[nbase + tid] = ebase + excl + d;
    dinv[nbase + tid] = rsqrtf(1.0f + (float)d);
    cur[tid] = ebase + excl;
    __syncthreads();
    for (int e = tid; e < 2048; e += 512) {
        int dd = dst[ebase + e] - nbase;
        int pos = atomicAdd(&cur[dd], 1);
        elist[pos] = src[ebase + e];
    }
}

// relabel + compact + next-stage CSR from global nid (runs on side stream)
__global__ __launch_bounds__(512) void k_csrN(const int* __restrict__ srcI,
                                              const int* __restrict__ dstI,
                                              const int* __restrict__ cntp,
                                              const int* __restrict__ nid, int k,
                                              int* __restrict__ srcO, int* __restrict__ dstO,
                                              int* __restrict__ gcntO,
                                              int* __restrict__ offs, int* __restrict__ endo,
                                              float* __restrict__ dinv, int* __restrict__ elist) {
    __shared__ unsigned short esrc[2048], edst[2048];
    __shared__ int deg[256], cur[256];
    __shared__ int scn[512];
    __shared__ int scnt;
    int b = blockIdx.x, tid = threadIdx.x;
    int ebase = b * 2048;
    int cnt = cntp ? cntp[b] : 2048;
    int bk = b * k;
    if (tid == 0) scnt = 0;
    if (tid < k) deg[tid] = 0;
    __syncthreads();
    for (int e = tid; e < cnt; e += 512) {
        int ns = nid[srcI[ebase + e]];
        int nd = nid[dstI[ebase + e]];
        if (ns >= 0 && nd >= 0) {
            int pos = atomicAdd(&scnt, 1);
            esrc[pos] = (unsigned short)ns;
            edst[pos] = (unsigned short)nd;
            srcO[ebase + pos] = bk + ns;
            dstO[ebase + pos] = bk + nd;
        }
    }
    __syncthreads();
    int ec = scnt;
    if (tid == 0) gcntO[b] = ec;
    for (int e = tid; e < ec; e += 512) atomicAdd(&deg[edst[e]], 1);
    __syncthreads();
    int d = (tid < k) ? deg[tid] : 0;
    scn[tid] = d;
    __syncthreads();
#pragma unroll
    for (int off = 1; off < 512; off <<= 1) {
        int v = (tid >= off) ? scn[tid - off] : 0;
        __syncthreads();
        scn[tid] += v;
        __syncthreads();
    }
    if (tid < k) {
        int excl = scn[tid] - d;
        offs[bk + tid] = ebase + excl;
        endo[bk + tid] = ebase + excl + d;
        dinv[bk + tid] = rsqrtf(1.0f + (float)d);
        cur[tid] = excl;
    }
    __syncthreads();
    for (int e = tid; e < ec; e += 512) {
        int pos = atomicAdd(&cur[edst[e]], 1);
        elist[ebase + pos] = bk + esrc[e];
    }
}

// fused: GCN aggregate + bias + ReLU + pool score. 1 warp/node.
__global__ __launch_bounds__(256) void k_node(const float* __restrict__ hW,
                                              const float* __restrict__ bias,
                                              const float* __restrict__ dinv,
                                              const int* __restrict__ offs,
                                              const int* __restrict__ endo,
                                              const int* __restrict__ elist,
                                              const float* __restrict__ p,
                                              const float* __restrict__ invn,
                                              float* __restrict__ h,
                                              float* __restrict__ score, int n) {
    __shared__ float ps[128];
    __shared__ float bs[128];
    int tid = threadIdx.x, lane = tid & 31, w = tid >> 5;
    if (tid < 128) { ps[tid] = p[tid]; bs[tid] = bias[tid]; }
    __syncthreads();
    int i = blockIdx.x * 8 + w;
    if (i >= n) return;
    float dii = dinv[i];
    float s2 = dii * dii;
    float4 acc = *(const float4*)&hW[(size_t)i * F + lane * 4];
    float4 bb = *(const float4*)&bs[lane * 4];
    acc.x = acc.x * s2 + bb.x; acc.y = acc.y * s2 + bb.y;
    acc.z = acc.z * s2 + bb.z; acc.w = acc.w * s2 + bb.w;
    float4 acc2 = make_float4(0.f, 0.f, 0.f, 0.f);
    int e = offs[i], ee = endo[i];
    for (; e + 1 < ee; e += 2) {
        int s0 = elist[e], s1 = elist[e + 1];
        float c0 = dinv[s0] * dii, c1 = dinv[s1] * dii;
        float4 v0 = *(const float4*)&hW[(size_t)s0 * F + lane * 4];
        float4 v1 = *(const float4*)&hW[(size_t)s1 * F + lane * 4];
        acc.x += v0.x * c0;  acc.y += v0.y * c0;
        acc.z += v0.z * c0;  acc.w += v0.w * c0;
        acc2.x += v1.x * c1; acc2.y += v1.y * c1;
        acc2.z += v1.z * c1; acc2.w += v1.w * c1;
    }
    if (e < ee) {
        int s0 = elist[e];
        float c0 = dinv[s0] * dii;
        float4 v0 = *(const float4*)&hW[(size_t)s0 * F + lane * 4];
        acc.x += v0.x * c0; acc.y += v0.y * c0;
        acc.z += v0.z * c0; acc.w += v0.w * c0;
    }
    acc.x += acc2.x; acc.y += acc2.y; acc.z += acc2.z; acc.w += acc2.w;
    acc.x = fmaxf(acc.x, 0.f); acc.y = fmaxf(acc.y, 0.f);
    acc.z = fmaxf(acc.z, 0.f); acc.w = fmaxf(acc.w, 0.f);
    *(float4*)&h[(size_t)i * F + lane * 4] = acc;
    float4 pv = *(const float4*)&ps[lane * 4];
    float d = acc.x * pv.x + acc.y * pv.y + acc.z * pv.z + acc.w * pv.w;
#pragma unroll
    for (int o = 16; o > 0; o >>= 1) d += __shfl_down_sync(0xffffffffu, d, o);
    if (lane == 0) score[i] = d * invn[0];
}

// light pooling: top-k + gather/readout (+ global nid write) (+ fused MLP on last stage)
__global__ __launch_bounds__(512) void k_pool(
    const float* __restrict__ score, int n_per, int k,
    const float* __restrict__ h, float* __restrict__ xk,
    float* __restrict__ z, int acc,
    int* __restrict__ nid_out,
    int do_mlp,
    const float* __restrict__ L1, const float* __restrict__ bl1,
    const float* __restrict__ L2, const float* __restrict__ bl2,
    const float* __restrict__ L3, const float* __restrict__ bl3,
    float* __restrict__ out) {
    __shared__ float sc[512];
    __shared__ int   id[512];
    __shared__ int   nid_s[512];
    __shared__ int   perm_s[256];
    __shared__ float tanh_s[256];
    __shared__ float mxb[512], smb[512];
    __shared__ float zr[256];
    __shared__ float h1[128];
    __shared__ float h2[64];
    __shared__ float lg[2];

    int b = blockIdx.x, tid = threadIdx.x;
    int nbase = b * n_per;

    sc[tid] = (tid < n_per) ? score[nbase + tid] : -INFINITY;
    id[tid] = tid;
    nid_s[tid] = -1;
    __syncthreads();
    for (int kk = 2; kk <= 512; kk <<= 1) {
        for (int j = kk >> 1; j > 0; j >>= 1) {
            int ixj = tid ^ j;
            if (ixj > tid) {
                bool dir = ((tid & kk) == 0);
                float s1 = sc[tid], s2 = sc[ixj];
                int i1 = id[tid], i2 = id[ixj];
                bool swp = dir ? ((s2 > s1) || (s2 == s1 && i2 < i1))
                               : ((s1 > s2) || (s1 == s2 && i1 < i2));
                if (swp) { sc[tid] = s2; sc[ixj] = s1; id[tid] = i2; id[ixj] = i1; }
            }
            __syncthreads();
        }
    }
    if (tid < k) {
        int loc = id[tid];
        perm_s[tid] = loc;
        tanh_s[tid] = tanhf(sc[tid]);
        nid_s[loc] = tid;
    }
    __syncthreads();
    if (nid_out && tid < n_per) nid_out[nbase + tid] = nid_s[tid];

    // gather + readout
    {
        int f = tid & 127, jj = tid >> 7;
        float mx = -INFINITY, sm = 0.f;
        for (int j = jj; j < k; j += 4) {
            float v = h[(size_t)(nbase + perm_s[j]) * F + f] * tanh_s[j];
            if (xk) xk[(size_t)(b * k + j) * F + f] = v;
            mx = fmaxf(mx, v);
            sm += v;
        }
        mxb[tid] = mx; smb[tid] = sm;
        __syncthreads();
        if (tid < 128) {
            mx = fmaxf(fmaxf(mxb[tid], mxb[tid + 128]), fmaxf(mxb[tid + 256], mxb[tid + 384]));
            sm = (smb[tid] + smb[tid + 128] + smb[tid + 256] + smb[tid + 384]) * (1.0f / (float)k);
            if (do_mlp) {
                zr[tid] = z[b * 256 + tid] + mx;          // acc implied
                zr[128 + tid] = z[b * 256 + 128 + tid] + sm;
            } else if (acc) {
                z[b * 256 + tid] += mx;
                z[b * 256 + 128 + tid] += sm;
            } else {
                z[b * 256 + tid] = mx;
                z[b * 256 + 128 + tid] = sm;
            }
        }
    }
    if (!do_mlp) return;
    __syncthreads();

    // fused MLP + log_softmax
    if (tid < 128) {
        float a = bl1[tid];
        for (int i = 0; i < 256; i++) a += zr[i] * L1[i * 128 + tid];
        h1[tid] = fmaxf(a, 0.f);
    }
    __syncthreads();
    if (tid < 64) {
        float a2 = bl2[tid];
        for (int i = 0; i < 128; i++) a2 += h1[i] * L2[i * 64 + tid];
        h2[tid] = fmaxf(a2, 0.f);
    }
    __syncthreads();
    if (tid < 2) {
        float a3 = bl3[tid];
        for (int i = 0; i < 64; i++) a3 += h2[i] * L3[i * 2 + tid];
        lg[tid] = a3;
    }
    __syncthreads();
    if (tid == 0) {
        float m = fmaxf(lg[0], lg[1]);
        float lse = m + logf(expf(lg[0] - m) + expf(lg[1] - m));
        out[b * 2 + 0] = lg[0] - lse;
        out[b * 2 + 1] = lg[1] - lse;
    }
}

// ---------------- host orchestration ----------------
extern "C" void kernel_launch(void* const* d_in, const int* in_sizes, int n_in,
                              void* d_out, int out_size) {
    const float* x   = (const float*)d_in[0];
    const int*   src = (const int*)d_in[1];
    const int*   dst = (const int*)d_in[2];
    const float* W1 = (const float*)d_in[3];  const float* b1 = (const float*)d_in[4];
    const float* W2 = (const float*)d_in[5];  const float* b2 = (const float*)d_in[6];
    const float* W3 = (const float*)d_in[7];  const float* b3 = (const float*)d_in[8];
    const float* p1 = (const float*)d_in[9];
    const float* p2 = (const float*)d_in[10];
    const float* p3 = (const float*)d_in[11];
    const float* L1 = (const float*)d_in[12]; const float* bl1 = (const float*)d_in[13];
    const float* L2 = (const float*)d_in[14]; const float* bl2 = (const float*)d_in[15];
    const float* L3 = (const float*)d_in[16]; const float* bl3 = (const float*)d_in[17];
    float* out = (float*)d_out;

    float *A, *B, *dinv, *score, *z, *invn;
    int *nid, *offs, *endo, *elist;
    int *srcA, *dstA, *srcB, *dstB, *gcnt2, *gcnt3;
    cudaGetSymbolAddress((void**)&A, g_bufA);
    cudaGetSymbolAddress((void**)&B, g_bufB);
    cudaGetSymbolAddress((void**)&dinv, g_dinv);
    cudaGetSymbolAddress((void**)&score, g_score);
    cudaGetSymbolAddress((void**)&nid, g_nid);
    cudaGetSymbolAddress((void**)&offs, g_offs);
    cudaGetSymbolAddress((void**)&endo, g_endo);
    cudaGetSymbolAddress((void**)&elist, g_elist);
    cudaGetSymbolAddress((void**)&srcA, g_srcA);
    cudaGetSymbolAddress((void**)&dstA, g_dstA);
    cudaGetSymbolAddress((void**)&srcB, g_srcB);
    cudaGetSymbolAddress((void**)&dstB, g_dstB);
    cudaGetSymbolAddress((void**)&gcnt2, g_gcnt2);
    cudaGetSymbolAddress((void**)&gcnt3, g_gcnt3);
    cudaGetSymbolAddress((void**)&z, g_z);
    cudaGetSymbolAddress((void**)&invn, g_invn);

    // one-time side stream + events (created on the non-captured correctness call)
    static cudaStream_t sside = nullptr;
    static cudaEvent_t ev[6];
    if (!sside) {
        cudaStreamCreateWithFlags(&sside, cudaStreamNonBlocking);
        for (int i = 0; i < 6; i++) cudaEventCreateWithFlags(&ev[i], cudaEventDisableTiming);
    }

    // ---------- stage 1: n=65536, n_per=512, k=256 ----------
    {
        const int n = 65536, n_per = 512, k = 256;
        // fork: csr1 (+pnorm) on side stream, gemm1 on main
        cudaEventRecord(ev[0], 0);
        cudaStreamWaitEvent(sside, ev[0], 0);
        k_csr<<<BATCH, 512, 0, sside>>>(src, dst, offs, endo, dinv, elist, p1, p2, p3, invn);
        cudaEventRecord(ev[1], sside);
        k_gemm_tc<<<n / 128, 256>>>(x, W1, A);
        cudaStreamWaitEvent(0, ev[1], 0);   // join before node1
        k_node<<<n / 8, 256>>>(A, b1, dinv, offs, endo, elist, p1, invn + 0, B, score, n);
        k_pool<<<BATCH, 512>>>(score, n_per, k, B, A, z, 0, nid,
                               0, nullptr, nullptr, nullptr, nullptr, nullptr, nullptr, nullptr);
        // fork: relabel+CSR on side, gemm2 on main
        cudaEventRecord(ev[2], 0);
        cudaStreamWaitEvent(sside, ev[2], 0);
        k_csrN<<<BATCH, 512, 0, sside>>>(src, dst, nullptr, nid, k,
                                         srcA, dstA, gcnt2, offs, endo, dinv, elist);
        cudaEventRecord(ev[3], sside);
    }
    // ---------- stage 2: n=32768, n_per=256, k=128 ----------
    {
        const int n = 32768, n_per = 256, k = 128;
        k_gemm_tc<<<n / 128, 256>>>(A, W2, B);
        cudaStreamWaitEvent(0, ev[3], 0);   // join before node2
        k_node<<<n / 8, 256>>>(B, b2, dinv, offs, endo, elist, p2, invn + 1, A, score, n);
        k_pool<<<BATCH, 512>>>(score, n_per, k, A, B, z, 1, nid,
                               0, nullptr, nullptr, nullptr, nullptr, nullptr, nullptr, nullptr);
        cudaEventRecord(ev[4], 0);
        cudaStreamWaitEvent(sside, ev[4], 0);
        k_csrN<<<BATCH, 512, 0, sside>>>(srcA, dstA, gcnt2, nid, k,
                                         srcB, dstB, gcnt3, offs, endo, dinv, elist);
        cudaEventRecord(ev[5], sside);
    }
    // ---------- stage 3: n=16384, n_per=128, k=64 ----------
    {
        const int n = 16384, n_per = 128, k = 64;
        k_gemm_tc<<<n / 128, 256>>>(B, W3, A);
        cudaStreamWaitEvent(0, ev[5], 0);   // join before node3
        k_node<<<n / 8, 256>>>(A, b3, dinv, offs, endo, elist, p3, invn + 2, B, score, n);
        k_pool<<<BATCH, 512>>>(score, n_per, k, B, nullptr, z, 1, nullptr,
                               1, L1, bl1, L2, bl2, L3, bl3, out);
    }
}

// round 17
// speedup vs baseline: 1.6785x; 1.0931x over previous
#include <cuda_runtime.h>
#include <cuda_bf16.h>
#include <cstdint>
#include <stdint.h>
#include <math.h>

#define BATCH   128
#define N0      512
#define E_TOT   262144
#define F       128
#define NMAX    65536

// ---------------- static scratch ----------------
__device__ float g_bufA[NMAX * F];
__device__ float g_bufB[NMAX * F];
__device__ float g_dinv[NMAX];
__device__ float g_score[NMAX];
__device__ int   g_nid[NMAX];
__device__ int   g_offs[NMAX];
__device__ int   g_endo[NMAX];
__device__ int   g_elist[E_TOT];
__device__ int   g_srcA[E_TOT], g_dstA[E_TOT];
__device__ int   g_srcB[E_TOT], g_dstB[E_TOT];
__device__ int   g_gcnt2[BATCH], g_gcnt3[BATCH];
__device__ float g_z[BATCH * 2 * F];
__device__ float g_invn[3];

// ---------------- helpers ----------------
__device__ __forceinline__ void split2(float x0, float x1, unsigned& hi, unsigned& lo) {
    __nv_bfloat16 h0 = __float2bfloat16(x0);
    __nv_bfloat16 h1 = __float2bfloat16(x1);
    __nv_bfloat16 l0 = __float2bfloat16(x0 - __bfloat162float(h0));
    __nv_bfloat16 l1 = __float2bfloat16(x1 - __bfloat162float(h1));
    hi = (unsigned)__bfloat16_as_ushort(h0) | ((unsigned)__bfloat16_as_ushort(h1) << 16);
    lo = (unsigned)__bfloat16_as_ushort(l0) | ((unsigned)__bfloat16_as_ushort(l1) << 16);
}

__device__ __forceinline__ void mma_bf16(float d[4], const unsigned a[4], const unsigned b[2]) {
    asm volatile(
        "mma.sync.aligned.m16n8k16.row.col.f32.bf16.bf16.f32 "
        "{%0,%1,%2,%3}, {%4,%5,%6,%7}, {%8,%9}, {%0,%1,%2,%3};\n"
        : "+f"(d[0]), "+f"(d[1]), "+f"(d[2]), "+f"(d[3])
        : "r"(a[0]), "r"(a[1]), "r"(a[2]), "r"(a[3]), "r"(b[0]), "r"(b[1]));
}

// ---------------- kernels ----------------

// GEMM (proven): 128x128 block tile, 8 warps, bf16x3, smem staged.
__global__ __launch_bounds__(256, 2) void k_gemm_tc(const float* __restrict__ X,
                                                    const float* __restrict__ W,
                                                    float* __restrict__ Y) {
    __shared__ uint2 Xs[128 * 12];
    __shared__ uint2 Ws[128 * 12];

    const int tid = threadIdx.x;
    const int lane = tid & 31;
    const int w = tid >> 5;
    const int g = lane >> 2;
    const int t4 = lane & 3;
    const int row0 = blockIdx.x * 128;
    const int mrow = w * 16;

    float d[16][4];
#pragma unroll
    for (int nt = 0; nt < 16; nt++)
#pragma unroll
        for (int j = 0; j < 4; j++) d[nt][j] = 0.f;

    const int xr = tid >> 1;
    const int xh = tid & 1;

    for (int kb = 0; kb < 128; kb += 16) {
        {
            const float* xrow = &X[(size_t)(row0 + xr) * 128 + kb + 8 * xh];
            float4 v1 = *(const float4*)&xrow[0];
            float4 v2 = *(const float4*)&xrow[4];
            unsigned h, l;
            split2(v1.x, v1.y, h, l); Xs[xr * 12 + 4 * xh + 0] = make_uint2(h, l);
            split2(v1.z, v1.w, h, l); Xs[xr * 12 + 4 * xh + 1] = make_uint2(h, l);
            split2(v2.x, v2.y, h, l); Xs[xr * 12 + 4 * xh + 2] = make_uint2(h, l);
            split2(v2.z, v2.w, h, l); Xs[xr * 12 + 4 * xh + 3] = make_uint2(h, l);
        }
        {
            int n = tid & 127, kh = tid >> 7;
#pragma unroll
            for (int j = 0; j < 4; j++) {
                int k = kb + 8 * kh + 2 * j;
                float w0 = W[(size_t)k * 128 + n];
                float w1 = W[(size_t)(k + 1) * 128 + n];
                unsigned h, l;
                split2(w0, w1, h, l);
                Ws[n * 12 + 4 * kh + j] = make_uint2(h, l);
            }
        }
        __syncthreads();
        {
            uint2 xa0 = Xs[(mrow + g) * 12 + t4];
            uint2 xa1 = Xs[(mrow + g + 8) * 12 + t4];
            uint2 xa2 = Xs[(mrow + g) * 12 + 4 + t4];
            uint2 xa3 = Xs[(mrow + g + 8) * 12 + 4 + t4];
            unsigned ahi[4] = {xa0.x, xa1.x, xa2.x, xa3.x};
            unsigned alo[4] = {xa0.y, xa1.y, xa2.y, xa3.y};
#pragma unroll
            for (int nt = 0; nt < 16; nt++) {
                uint2 wb0 = Ws[(nt * 8 + g) * 12 + t4];
                uint2 wb1 = Ws[(nt * 8 + g) * 12 + 4 + t4];
                unsigned bhi[2] = {wb0.x, wb1.x};
                unsigned blo[2] = {wb0.y, wb1.y};
                mma_bf16(d[nt], ahi, bhi);
                mma_bf16(d[nt], ahi, blo);
                mma_bf16(d[nt], alo, bhi);
            }
        }
        __syncthreads();
    }

#pragma unroll
    for (int nt = 0; nt < 16; nt++) {
        const int n0 = nt * 8;
        float* y0 = &Y[(size_t)(row0 + mrow + g) * 128 + n0 + 2 * t4];
        float* y1 = &Y[(size_t)(row0 + mrow + g + 8) * 128 + n0 + 2 * t4];
        *(float2*)y0 = make_float2(d[nt][0], d[nt][1]);
        *(float2*)y1 = make_float2(d[nt][2], d[nt][3]);
    }
}

// stage-1 CSR from raw edges (1 block/graph) + fused pnorm (block 0, warps 0-2)
__global__ __launch_bounds__(512) void k_csr(const int* __restrict__ src,
                                             const int* __restrict__ dst,
                                             int* __restrict__ offs, int* __restrict__ endo,
                                             float* __restrict__ dinv, int* __restrict__ elist,
                                             const float* __restrict__ p1,
                                             const float* __restrict__ p2,
                                             const float* __restrict__ p3,
                                             float* __restrict__ invn) {
    __shared__ int deg[512];
    __shared__ int scn[512];
    __shared__ int cur[512];
    int b = blockIdx.x, tid = threadIdx.x;
    int lane = tid & 31, wid = tid >> 5;
    if (b == 0 && wid < 3) {
        const float* pp = (wid == 0) ? p1 : ((wid == 1) ? p2 : p3);
        float s = 0.f;
        for (int q = lane; q < 128; q += 32) { float v = pp[q]; s += v * v; }
#pragma unroll
        for (int o = 16; o > 0; o >>= 1) s += __shfl_down_sync(0xffffffffu, s, o);
        if (lane == 0) invn[wid] = rsqrtf(s);
    }
    int nbase = b * 512;
    int ebase = b * 2048;
    deg[tid] = 0;
    __syncthreads();
    for (int e = tid; e < 2048; e += 512)
        atomicAdd(&deg[dst[ebase + e] - nbase], 1);
    __syncthreads();
    int d = deg[tid];
    scn[tid] = d;
    __syncthreads();
#pragma unroll
    for (int off = 1; off < 512; off <<= 1) {
        int v = (tid >= off) ? scn[tid - off] : 0;
        __syncthreads();
        scn[tid] += v;
        __syncthreads();
    }
    int excl = scn[tid] - d;
    offs[nbase + tid] = ebase + excl;
    endo[nbase + tid] = ebase + excl + d;
    dinv[nbase + tid] = rsqrtf(1.0f + (float)d);
    cur[tid] = ebase + excl;
    __syncthreads();
    for (int e = tid; e < 2048; e += 512) {
        int dd = dst[ebase + e] - nbase;
        int pos = atomicAdd(&cur[dd], 1);
        elist[pos] = src[ebase + e];
    }
}

// relabel + compact + next-stage CSR from global nid (runs on side stream)
__global__ __launch_bounds__(512) void k_csrN(const int* __restrict__ srcI,
                                              const int* __restrict__ dstI,
                                              const int* __restrict__ cntp,
                                              const int* __restrict__ nid, int k,
                                              int* __restrict__ srcO, int* __restrict__ dstO,
                                              int* __restrict__ gcntO,
                                              int* __restrict__ offs, int* __restrict__ endo,
                                              float* __restrict__ dinv, int* __restrict__ elist) {
    __shared__ unsigned short esrc[2048], edst[2048];
    __shared__ int deg[256], cur[256];
    __shared__ int scn[512];
    __shared__ int scnt;
    int b = blockIdx.x, tid = threadIdx.x;
    int ebase = b * 2048;
    int cnt = cntp ? cntp[b] : 2048;
    int bk = b * k;
    if (tid == 0) scnt = 0;
    if (tid < k) deg[tid] = 0;
    __syncthreads();
    for (int e = tid; e < cnt; e += 512) {
        int ns = nid[srcI[ebase + e]];
        int nd = nid[dstI[ebase + e]];
        if (ns >= 0 && nd >= 0) {
            int pos = atomicAdd(&scnt, 1);
            esrc[pos] = (unsigned short)ns;
            edst[pos] = (unsigned short)nd;
            srcO[ebase + pos] = bk + ns;
            dstO[ebase + pos] = bk + nd;
        }
    }
    __syncthreads();
    int ec = scnt;
    if (tid == 0) gcntO[b] = ec;
    for (int e = tid; e < ec; e += 512) atomicAdd(&deg[edst[e]], 1);
    __syncthreads();
    int d = (tid < k) ? deg[tid] : 0;
    scn[tid] = d;
    __syncthreads();
#pragma unroll
    for (int off = 1; off < 512; off <<= 1) {
        int v = (tid >= off) ? scn[tid - off] : 0;
        __syncthreads();
        scn[tid] += v;
        __syncthreads();
    }
    if (tid < k) {
        int excl = scn[tid] - d;
        offs[bk + tid] = ebase + excl;
        endo[bk + tid] = ebase + excl + d;
        dinv[bk + tid] = rsqrtf(1.0f + (float)d);
        cur[tid] = excl;
    }
    __syncthreads();
    for (int e = tid; e < ec; e += 512) {
        int pos = atomicAdd(&cur[edst[e]], 1);
        elist[ebase + pos] = bk + esrc[e];
    }
}

// fused: GCN aggregate + bias + ReLU + pool score. 1 warp/node.
__global__ __launch_bounds__(256) void k_node(const float* __restrict__ hW,
                                              const float* __restrict__ bias,
                                              const float* __restrict__ dinv,
                                              const int* __restrict__ offs,
                                              const int* __restrict__ endo,
                                              const int* __restrict__ elist,
                                              const float* __restrict__ p,
                                              const float* __restrict__ invn,
                                              float* __restrict__ h,
                                              float* __restrict__ score, int n) {
    __shared__ float ps[128];
    __shared__ float bs[128];
    int tid = threadIdx.x, lane = tid & 31, w = tid >> 5;
    if (tid < 128) { ps[tid] = p[tid]; bs[tid] = bias[tid]; }
    __syncthreads();
    int i = blockIdx.x * 8 + w;
    if (i >= n) return;
    float dii = dinv[i];
    float s2 = dii * dii;
    float4 acc = *(const float4*)&hW[(size_t)i * F + lane * 4];
    float4 bb = *(const float4*)&bs[lane * 4];
    acc.x = acc.x * s2 + bb.x; acc.y = acc.y * s2 + bb.y;
    acc.z = acc.z * s2 + bb.z; acc.w = acc.w * s2 + bb.w;
    float4 acc2 = make_float4(0.f, 0.f, 0.f, 0.f);
    int e = offs[i], ee = endo[i];
    for (; e + 1 < ee; e += 2) {
        int s0 = elist[e], s1 = elist[e + 1];
        float c0 = dinv[s0] * dii, c1 = dinv[s1] * dii;
        float4 v0 = *(const float4*)&hW[(size_t)s0 * F + lane * 4];
        float4 v1 = *(const float4*)&hW[(size_t)s1 * F + lane * 4];
        acc.x += v0.x * c0;  acc.y += v0.y * c0;
        acc.z += v0.z * c0;  acc.w += v0.w * c0;
        acc2.x += v1.x * c1; acc2.y += v1.y * c1;
        acc2.z += v1.z * c1; acc2.w += v1.w * c1;
    }
    if (e < ee) {
        int s0 = elist[e];
        float c0 = dinv[s0] * dii;
        float4 v0 = *(const float4*)&hW[(size_t)s0 * F + lane * 4];
        acc.x += v0.x * c0; acc.y += v0.y * c0;
        acc.z += v0.z * c0; acc.w += v0.w * c0;
    }
    acc.x += acc2.x; acc.y += acc2.y; acc.z += acc2.z; acc.w += acc2.w;
    acc.x = fmaxf(acc.x, 0.f); acc.y = fmaxf(acc.y, 0.f);
    acc.z = fmaxf(acc.z, 0.f); acc.w = fmaxf(acc.w, 0.f);
    *(float4*)&h[(size_t)i * F + lane * 4] = acc;
    float4 pv = *(const float4*)&ps[lane * 4];
    float d = acc.x * pv.x + acc.y * pv.y + acc.z * pv.z + acc.w * pv.w;
#pragma unroll
    for (int o = 16; o > 0; o >>= 1) d += __shfl_down_sync(0xffffffffu, d, o);
    if (lane == 0) score[i] = d * invn[0];
}

// light pooling: hybrid bitonic top-k + gather/readout (+ nid write) (+ fused MLP)
__global__ __launch_bounds__(512) void k_pool(
    const float* __restrict__ score, int n_per, int k,
    const float* __restrict__ h, float* __restrict__ xk,
    float* __restrict__ z, int acc,
    int* __restrict__ nid_out,
    int do_mlp,
    const float* __restrict__ L1, const float* __restrict__ bl1,
    const float* __restrict__ L2, const float* __restrict__ bl2,
    const float* __restrict__ L3, const float* __restrict__ bl3,
    float* __restrict__ out) {
    __shared__ float sc[512];
    __shared__ int   id[512];
    __shared__ int   nid_s[512];
    __shared__ int   perm_s[256];
    __shared__ float tanh_s[256];
    __shared__ float mxb[512], smb[512];
    __shared__ float zr[256];
    __shared__ float h1[128];
    __shared__ float h2[64];
    __shared__ float lg[2];

    int b = blockIdx.x, tid = threadIdx.x;
    int nbase = b * n_per;

    float s = (tid < n_per) ? score[nbase + tid] : -INFINITY;
    int i = tid;
    nid_s[tid] = -1;

    // ---- levels kk=2..32: all intra-warp, register-only, zero barriers ----
#pragma unroll
    for (int kk = 2; kk <= 32; kk <<= 1) {
#pragma unroll
        for (int j = kk >> 1; j >= 1; j >>= 1) {
            float s2 = __shfl_xor_sync(0xffffffffu, s, j);
            int i2 = __shfl_xor_sync(0xffffffffu, i, j);
            bool up = ((tid & j) == 0);
            bool dir = ((tid & kk) == 0);
            bool self_earlier = (s > s2) || (s == s2 && i < i2);
            if (self_earlier != (up == dir)) { s = s2; i = i2; }
        }
    }
    sc[tid] = s; id[tid] = i;
    __syncthreads();

    // ---- levels kk=64..512: smem stages j>=32, then register tail j<=16 ----
#pragma unroll
    for (int kk = 64; kk <= 512; kk <<= 1) {
        for (int j = kk >> 1; j >= 32; j >>= 1) {
            int ixj = tid ^ j;
            if (ixj > tid) {
                bool dir = ((tid & kk) == 0);
                float s1 = sc[tid], sx = sc[ixj];
                int i1 = id[tid], ix = id[ixj];
                bool swp = dir ? ((sx > s1) || (sx == s1 && ix < i1))
                               : ((s1 > sx) || (s1 == sx && i1 < ix));
                if (swp) { sc[tid] = sx; sc[ixj] = s1; id[tid] = ix; id[ixj] = i1; }
            }
            __syncthreads();
        }
        s = sc[tid]; i = id[tid];
#pragma unroll
        for (int j = 16; j >= 1; j >>= 1) {
            float s2 = __shfl_xor_sync(0xffffffffu, s, j);
            int i2 = __shfl_xor_sync(0xffffffffu, i, j);
            bool up = ((tid & j) == 0);
            bool dir = ((tid & kk) == 0);
            bool self_earlier = (s > s2) || (s == s2 && i < i2);
            if (self_earlier != (up == dir)) { s = s2; i = i2; }
        }
        sc[tid] = s; id[tid] = i;
        __syncthreads();
    }

    if (tid < k) {
        int loc = id[tid];
        perm_s[tid] = loc;
        tanh_s[tid] = tanhf(sc[tid]);
        nid_s[loc] = tid;
    }
    __syncthreads();
    if (nid_out && tid < n_per) nid_out[nbase + tid] = nid_s[tid];

    // gather + readout
    {
        int f = tid & 127, jj = tid >> 7;
        float mx = -INFINITY, sm = 0.f;
        for (int j = jj; j < k; j += 4) {
            float v = h[(size_t)(nbase + perm_s[j]) * F + f] * tanh_s[j];
            if (xk) xk[(size_t)(b * k + j) * F + f] = v;
            mx = fmaxf(mx, v);
            sm += v;
        }
        mxb[tid] = mx; smb[tid] = sm;
        __syncthreads();
        if (tid < 128) {
            mx = fmaxf(fmaxf(mxb[tid], mxb[tid + 128]), fmaxf(mxb[tid + 256], mxb[tid + 384]));
            sm = (smb[tid] + smb[tid + 128] + smb[tid + 256] + smb[tid + 384]) * (1.0f / (float)k);
            if (do_mlp) {
                zr[tid] = z[b * 256 + tid] + mx;
                zr[128 + tid] = z[b * 256 + 128 + tid] + sm;
            } else if (acc) {
                z[b * 256 + tid] += mx;
                z[b * 256 + 128 + tid] += sm;
            } else {
                z[b * 256 + tid] = mx;
                z[b * 256 + 128 + tid] = sm;
            }
        }
    }
    if (!do_mlp) return;
    __syncthreads();

    if (tid < 128) {
        float a = bl1[tid];
        for (int q = 0; q < 256; q++) a += zr[q] * L1[q * 128 + tid];
        h1[tid] = fmaxf(a, 0.f);
    }
    __syncthreads();
    if (tid < 64) {
        float a2 = bl2[tid];
        for (int q = 0; q < 128; q++) a2 += h1[q] * L2[q * 64 + tid];
        h2[tid] = fmaxf(a2, 0.f);
    }
    __syncthreads();
    if (tid < 2) {
        float a3 = bl3[tid];
        for (int q = 0; q < 64; q++) a3 += h2[q] * L3[q * 2 + tid];
        lg[tid] = a3;
    }
    __syncthreads();
    if (tid == 0) {
        float m = fmaxf(lg[0], lg[1]);
        float lse = m + logf(expf(lg[0] - m) + expf(lg[1] - m));
        out[b * 2 + 0] = lg[0] - lse;
        out[b * 2 + 1] = lg[1] - lse;
    }
}

// ---------------- host orchestration ----------------
extern "C" void kernel_launch(void* const* d_in, const int* in_sizes, int n_in,
                              void* d_out, int out_size) {
    const float* x   = (const float*)d_in[0];
    const int*   src = (const int*)d_in[1];
    const int*   dst = (const int*)d_in[2];
    const float* W1 = (const float*)d_in[3];  const float* b1 = (const float*)d_in[4];
    const float* W2 = (const float*)d_in[5];  const float* b2 = (const float*)d_in[6];
    const float* W3 = (const float*)d_in[7];  const float* b3 = (const float*)d_in[8];
    const float* p1 = (const float*)d_in[9];
    const float* p2 = (const float*)d_in[10];
    const float* p3 = (const float*)d_in[11];
    const float* L1 = (const float*)d_in[12]; const float* bl1 = (const float*)d_in[13];
    const float* L2 = (const float*)d_in[14]; const float* bl2 = (const float*)d_in[15];
    const float* L3 = (const float*)d_in[16]; const float* bl3 = (const float*)d_in[17];
    float* out = (float*)d_out;

    float *A, *B, *dinv, *score, *z, *invn;
    int *nid, *offs, *endo, *elist;
    int *srcA, *dstA, *srcB, *dstB, *gcnt2, *gcnt3;
    cudaGetSymbolAddress((void**)&A, g_bufA);
    cudaGetSymbolAddress((void**)&B, g_bufB);
    cudaGetSymbolAddress((void**)&dinv, g_dinv);
    cudaGetSymbolAddress((void**)&score, g_score);
    cudaGetSymbolAddress((void**)&nid, g_nid);
    cudaGetSymbolAddress((void**)&offs, g_offs);
    cudaGetSymbolAddress((void**)&endo, g_endo);
    cudaGetSymbolAddress((void**)&elist, g_elist);
    cudaGetSymbolAddress((void**)&srcA, g_srcA);
    cudaGetSymbolAddress((void**)&dstA, g_dstA);
    cudaGetSymbolAddress((void**)&srcB, g_srcB);
    cudaGetSymbolAddress((void**)&dstB, g_dstB);
    cudaGetSymbolAddress((void**)&gcnt2, g_gcnt2);
    cudaGetSymbolAddress((void**)&gcnt3, g_gcnt3);
    cudaGetSymbolAddress((void**)&z, g_z);
    cudaGetSymbolAddress((void**)&invn, g_invn);

    static cudaStream_t sside = nullptr;
    static cudaEvent_t ev[6];
    if (!sside) {
        cudaStreamCreateWithFlags(&sside, cudaStreamNonBlocking);
        for (int i = 0; i < 6; i++) cudaEventCreateWithFlags(&ev[i], cudaEventDisableTiming);
    }

    // ---------- stage 1: n=65536, n_per=512, k=256 ----------
    {
        const int n = 65536, n_per = 512, k = 256;
        cudaEventRecord(ev[0], 0);
        cudaStreamWaitEvent(sside, ev[0], 0);
        k_csr<<<BATCH, 512, 0, sside>>>(src, dst, offs, endo, dinv, elist, p1, p2, p3, invn);
        cudaEventRecord(ev[1], sside);
        k_gemm_tc<<<n / 128, 256>>>(x, W1, A);
        cudaStreamWaitEvent(0, ev[1], 0);
        k_node<<<n / 8, 256>>>(A, b1, dinv, offs, endo, elist, p1, invn + 0, B, score, n);
        k_pool<<<BATCH, 512>>>(score, n_per, k, B, A, z, 0, nid,
                               0, nullptr, nullptr, nullptr, nullptr, nullptr, nullptr, nullptr);
        cudaEventRecord(ev[2], 0);
        cudaStreamWaitEvent(sside, ev[2], 0);
        k_csrN<<<BATCH, 512, 0, sside>>>(src, dst, nullptr, nid, k,
                                         srcA, dstA, gcnt2, offs, endo, dinv, elist);
        cudaEventRecord(ev[3], sside);
    }
    // ---------- stage 2: n=32768, n_per=256, k=128 ----------
    {
        const int n = 32768, n_per = 256, k = 128;
        k_gemm_tc<<<n / 128, 256>>>(A, W2, B);
        cudaStreamWaitEvent(0, ev[3], 0);
        k_node<<<n / 8, 256>>>(B, b2, dinv, offs, endo, elist, p2, invn + 1, A, score, n);
        k_pool<<<BATCH, 512>>>(score, n_per, k, A, B, z, 1, nid,
                               0, nullptr, nullptr, nullptr, nullptr, nullptr, nullptr, nullptr);
        cudaEventRecord(ev[4], 0);
        cudaStreamWaitEvent(sside, ev[4], 0);
        k_csrN<<<BATCH, 512, 0, sside>>>(srcA, dstA, gcnt2, nid, k,
                                         srcB, dstB, gcnt3, offs, endo, dinv, elist);
        cudaEventRecord(ev[5], sside);
    }
    // ---------- stage 3: n=16384, n_per=128, k=64 ----------
    {
        const int n = 16384, n_per = 128, k = 64;
        k_gemm_tc<<<n / 128, 256>>>(B, W3, A);
        cudaStreamWaitEvent(0, ev[5], 0);
        k_node<<<n / 8, 256>>>(A, b3, dinv, offs, endo, elist, p3, invn + 2, B, score, n);
        k_pool<<<BATCH, 512>>>(score, n_per, k, B, nullptr, z, 1, nullptr,
                               1, L1, bl1, L2, bl2, L3, bl3, out);
    }
}